// round 1
// baseline (speedup 1.0000x reference)
#include <cuda_runtime.h>
#include <math.h>

// Problem constants
#define B_  16
#define T_  4096
#define D_  1024
#define U_  1024
#define M_  (B_ * T_)   // 65536 rows of the fused GEMM

// Scratch (device globals — no allocations allowed)
__device__ float g_hpb[B_ * U_];    // h@W1 + b1 + b2, per (b,u)
__device__ float g_score[M_];       // pre-softmax scores

// ---------------------------------------------------------------------------
// Kernel 1: hpb[b,u] = sum_d h[b,d] * W1[d,u] + b1[u] + b2[u]
// grid (U/256, B), 256 threads
// ---------------------------------------------------------------------------
__global__ void hproj_kernel(const float* __restrict__ h,
                             const float* __restrict__ W1,
                             const float* __restrict__ b1,
                             const float* __restrict__ b2) {
    __shared__ float hs[D_];
    const int b = blockIdx.y;
    const int u = blockIdx.x * 256 + threadIdx.x;
    for (int i = threadIdx.x; i < D_; i += 256) hs[i] = h[b * D_ + i];
    __syncthreads();
    float acc = 0.f;
    #pragma unroll 8
    for (int d = 0; d < D_; d++) acc = fmaf(hs[d], W1[d * U_ + u], acc);
    g_hpb[b * U_ + u] = acc + b1[u] + b2[u];
}

// ---------------------------------------------------------------------------
// Kernel 2: fused score GEMM.
//   score[row] = sum_u V[u] * tanh( enc_row . W2[:,u] + hpb[b,u] )
// Register-blocked SGEMM: BM=128, BN=128, BK=16, 256 thr, 8x8 per thread.
// Each block owns 128 rows and loops over all 8 u-tiles, carrying the
// V-weighted tanh reduction in registers. One clean store per row at the end.
// ---------------------------------------------------------------------------
#define BM 128
#define BN 128
#define BK 16
#define TM 8
#define TN 8

__global__ __launch_bounds__(256)
void score_kernel(const float* __restrict__ X,    // enc as [M_, D_]
                  const float* __restrict__ W2,   // [D_, U_]
                  const float* __restrict__ V) {  // [U_]
    const int row0 = blockIdx.x * BM;
    const int b    = row0 >> 12;                  // 4096 rows per batch

    __shared__ float As[BK][BM];                  // X tile, k-major
    __shared__ float Bs[BK][BN];                  // W2 tile, k-major

    const int tid = threadIdx.x;
    const int tx  = tid & 15;                     // u direction
    const int ty  = tid >> 4;                     // t direction

    float partial[TM];
    #pragma unroll
    for (int i = 0; i < TM; i++) partial[i] = 0.f;

    for (int un = 0; un < U_; un += BN) {
        float acc[TM][TN];
        #pragma unroll
        for (int i = 0; i < TM; i++)
            #pragma unroll
            for (int j = 0; j < TN; j++) acc[i][j] = 0.f;

        for (int k0 = 0; k0 < D_; k0 += BK) {
            // Load X tile: 128 rows x 16 k  (2 float4 per thread)
            #pragma unroll
            for (int p = 0; p < 2; p++) {
                const int r  = p * 64 + (tid >> 2);
                const int kk = (tid & 3) * 4;
                const float4 v4 = *(const float4*)(X + (size_t)(row0 + r) * D_ + k0 + kk);
                As[kk + 0][r] = v4.x;
                As[kk + 1][r] = v4.y;
                As[kk + 2][r] = v4.z;
                As[kk + 3][r] = v4.w;
            }
            // Load W2 tile: 16 k x 128 u  (2 float4 per thread)
            #pragma unroll
            for (int p = 0; p < 2; p++) {
                const int kk = p * 8 + (tid >> 5);
                const int c  = (tid & 31) * 4;
                *(float4*)&Bs[kk][c] =
                    *(const float4*)(W2 + (size_t)(k0 + kk) * U_ + un + c);
            }
            __syncthreads();

            #pragma unroll
            for (int k = 0; k < BK; k++) {
                float af[TM], bf[TN];
                #pragma unroll
                for (int i = 0; i < TM; i++) af[i] = As[k][ty * TM + i];
                #pragma unroll
                for (int j = 0; j < TN; j++) bf[j] = Bs[k][tx * TN + j];
                #pragma unroll
                for (int i = 0; i < TM; i++)
                    #pragma unroll
                    for (int j = 0; j < TN; j++)
                        acc[i][j] = fmaf(af[i], bf[j], acc[i][j]);
            }
            __syncthreads();
        }

        // Epilogue for this u-tile: fold tanh + V into running row partials.
        #pragma unroll
        for (int j = 0; j < TN; j++) {
            const int u = un + tx * TN + j;
            const float hv = g_hpb[b * U_ + u];
            const float vv = V[u];
            #pragma unroll
            for (int i = 0; i < TM; i++)
                partial[i] += vv * tanhf(acc[i][j] + hv);
        }
    }

    // Reduce partials across the 16 tx-threads (half-warp segments).
    #pragma unroll
    for (int i = 0; i < TM; i++) {
        float v = partial[i];
        #pragma unroll
        for (int off = 8; off > 0; off >>= 1)
            v += __shfl_down_sync(0xffffffffu, v, off, 16);
        if (tx == 0) g_score[row0 + ty * TM + i] = v;
    }
}

// ---------------------------------------------------------------------------
// Kernel 3: softmax over T per batch. Writes weights into the output buffer.
// (bv is a constant shift -> softmax-invariant -> omitted.)
// ---------------------------------------------------------------------------
__global__ void softmax_kernel(float* __restrict__ wout) {
    const int b = blockIdx.x;
    const float* s = g_score + b * T_;
    float* w = wout + b * T_;
    __shared__ float red[256];
    const int tid = threadIdx.x;

    float mx = -INFINITY;
    for (int t = tid; t < T_; t += 256) mx = fmaxf(mx, s[t]);
    red[tid] = mx; __syncthreads();
    for (int o = 128; o > 0; o >>= 1) {
        if (tid < o) red[tid] = fmaxf(red[tid], red[tid + o]);
        __syncthreads();
    }
    mx = red[0]; __syncthreads();

    float sum = 0.f;
    for (int t = tid; t < T_; t += 256) {
        const float e = expf(s[t] - mx);
        w[t] = e;
        sum += e;
    }
    red[tid] = sum; __syncthreads();
    for (int o = 128; o > 0; o >>= 1) {
        if (tid < o) red[tid] += red[tid + o];
        __syncthreads();
    }
    const float inv = 1.f / red[0];
    for (int t = tid; t < T_; t += 256) w[t] *= inv;
}

// ---------------------------------------------------------------------------
// Kernel 4: context[b,d] = sum_t w[b,t] * enc[b,t,d]
// grid (T/128, B), 256 threads; each thread owns 4 d-columns, atomicAdd.
// ---------------------------------------------------------------------------
__global__ void context_kernel(const float* __restrict__ enc,
                               const float* __restrict__ w,
                               float* __restrict__ ctx) {
    const int b  = blockIdx.y;
    const int t0 = blockIdx.x * 128;
    const int tid = threadIdx.x;
    float c[4] = {0.f, 0.f, 0.f, 0.f};
    for (int t = t0; t < t0 + 128; t++) {
        const float wt = w[b * T_ + t];
        const float* row = enc + ((size_t)b * T_ + t) * D_;
        #pragma unroll
        for (int j = 0; j < 4; j++)
            c[j] = fmaf(wt, row[tid + j * 256], c[j]);
    }
    #pragma unroll
    for (int j = 0; j < 4; j++)
        atomicAdd(&ctx[b * D_ + tid + j * 256], c[j]);
}

// ---------------------------------------------------------------------------
extern "C" void kernel_launch(void* const* d_in, const int* in_sizes, int n_in,
                              void* d_out, int out_size) {
    const float* h   = (const float*)d_in[0];  // [B, D]
    const float* enc = (const float*)d_in[1];  // [B, T, D]
    const float* W1  = (const float*)d_in[2];  // [D, U]
    const float* b1  = (const float*)d_in[3];  // [U]
    const float* W2  = (const float*)d_in[4];  // [D, U]
    const float* b2  = (const float*)d_in[5];  // [U]
    const float* V   = (const float*)d_in[6];  // [U, 1]
    // d_in[7] = bv: constant shift, softmax-invariant -> unused.

    float* out = (float*)d_out;
    float* ctx = out;             // [B, D]   = 16384 floats
    float* wts = out + B_ * D_;   // [B, T, 1] = 65536 floats

    cudaMemsetAsync(ctx, 0, (size_t)B_ * D_ * sizeof(float));

    hproj_kernel<<<dim3(U_ / 256, B_), 256>>>(h, W1, b1, b2);
    score_kernel<<<M_ / BM, 256>>>(enc, W2, V);
    softmax_kernel<<<B_, 256>>>(wts);
    context_kernel<<<dim3(T_ / 128, B_), 256>>>(enc, wts, ctx);
}

// round 3
// speedup vs baseline: 2.3107x; 2.3107x over previous
#include <cuda_runtime.h>
#include <cuda_bf16.h>
#include <math.h>
#include <stdint.h>

// Problem constants
#define B_  16
#define T_  4096
#define D_  1024
#define U_  1024
#define M_  (B_ * T_)   // 65536 rows

// ---------------------------------------------------------------------------
// Device-global scratch (no allocations allowed)
// ---------------------------------------------------------------------------
__device__ __nv_bfloat16 g_Xhi[(size_t)M_ * D_];   // 128 MiB
__device__ __nv_bfloat16 g_Xlo[(size_t)M_ * D_];   // 128 MiB
__device__ __nv_bfloat16 g_Whi[(size_t)U_ * D_];   // W2^T [u][d]
__device__ __nv_bfloat16 g_Wlo[(size_t)U_ * D_];
__device__ float g_hpb[B_ * U_];
__device__ float g_score[M_];

// ---------------------------------------------------------------------------
// Helpers
// ---------------------------------------------------------------------------
__device__ __forceinline__ uint32_t smem_u32(const void* p) {
    uint32_t a;
    asm("{ .reg .u64 t; cvta.to.shared.u64 t, %1; cvt.u32.u64 %0, t; }" : "=r"(a) : "l"(p));
    return a;
}
#define CP_ASYNC16(dst, src) \
    asm volatile("cp.async.cg.shared.global [%0], [%1], 16;" :: "r"(dst), "l"(src))
#define CP_COMMIT() asm volatile("cp.async.commit_group;" ::: "memory")
#define CP_WAIT1()  asm volatile("cp.async.wait_group 1;" ::: "memory")

__device__ __forceinline__ void ldm_x4(uint32_t* r, uint32_t addr) {
    asm volatile("ldmatrix.sync.aligned.m8n8.x4.shared.b16 {%0,%1,%2,%3}, [%4];"
                 : "=r"(r[0]), "=r"(r[1]), "=r"(r[2]), "=r"(r[3]) : "r"(addr));
}
__device__ __forceinline__ void mma_bf16(float* c, const uint32_t* a, const uint32_t* b) {
    asm volatile(
        "mma.sync.aligned.m16n8k16.row.col.f32.bf16.bf16.f32 "
        "{%0,%1,%2,%3}, {%4,%5,%6,%7}, {%8,%9}, {%0,%1,%2,%3};"
        : "+f"(c[0]), "+f"(c[1]), "+f"(c[2]), "+f"(c[3])
        : "r"(a[0]), "r"(a[1]), "r"(a[2]), "r"(a[3]), "r"(b[0]), "r"(b[1]));
}

// FMA-only fast tanh (abs err ~1e-6); avoids MUFU entirely.
__device__ __forceinline__ float fast_tanh(float x) {
    float ax = fabsf(x);
    float t = fminf(ax * 2.885390082f, 30.0f);     // 2|x|*log2(e)
    float nt = -t;
    float fi = floorf(nt);
    float f = nt - fi;                              // [0,1)
    float p =              1.5253232e-5f;
    p = fmaf(p, f, 1.5403530e-4f);
    p = fmaf(p, f, 1.3333558e-3f);
    p = fmaf(p, f, 9.6181291e-3f);
    p = fmaf(p, f, 5.5504109e-2f);
    p = fmaf(p, f, 2.4022651e-1f);
    p = fmaf(p, f, 6.9314718e-1f);
    p = fmaf(p, f, 1.0f);
    int ei = (int)fi;                               // [-30, 0]
    float e = __int_as_float((ei + 127) << 23) * p; // 2^nt = e^{-2|x|}
    float d = 1.0f + e;
    float r = __int_as_float(0x7EF311C3u - __float_as_int(d));
    r = r * (2.0f - d * r);
    r = r * (2.0f - d * r);
    r = r * (2.0f - d * r);
    float y = (1.0f - e) * r;
    return copysignf(y, x);
}

// ---------------------------------------------------------------------------
// Kernel A: split enc fp32 -> bf16 hi/lo
// ---------------------------------------------------------------------------
__global__ void convert_x_kernel(const float* __restrict__ X) {
    size_t i = ((size_t)blockIdx.x * 256 + threadIdx.x) * 8;
    float4 a = *(const float4*)(X + i);
    float4 b = *(const float4*)(X + i + 4);
    float v[8] = {a.x, a.y, a.z, a.w, b.x, b.y, b.z, b.w};
    __nv_bfloat16 hi[8], lo[8];
    #pragma unroll
    for (int j = 0; j < 8; j++) {
        hi[j] = __float2bfloat16(v[j]);
        lo[j] = __float2bfloat16(v[j] - __bfloat162float(hi[j]));
    }
    *(uint4*)(g_Xhi + i) = *(uint4*)hi;
    *(uint4*)(g_Xlo + i) = *(uint4*)lo;
}

// ---------------------------------------------------------------------------
// Kernel B: transpose + split W2 [d][u] -> [u][d] bf16 hi/lo
// ---------------------------------------------------------------------------
__global__ void convert_w_kernel(const float* __restrict__ W2) {
    __shared__ float tile[32][33];
    const int u0 = blockIdx.x * 32, d0 = blockIdx.y * 32;
    const int tx = threadIdx.x, ty = threadIdx.y;           // (32, 8)
    #pragma unroll
    for (int j = 0; j < 32; j += 8)
        tile[ty + j][tx] = W2[(size_t)(d0 + ty + j) * U_ + u0 + tx];
    __syncthreads();
    #pragma unroll
    for (int j = 0; j < 32; j += 8) {
        float v = tile[tx][ty + j];
        __nv_bfloat16 h = __float2bfloat16(v);
        __nv_bfloat16 l = __float2bfloat16(v - __bfloat162float(h));
        g_Whi[(size_t)(u0 + ty + j) * D_ + d0 + tx] = h;
        g_Wlo[(size_t)(u0 + ty + j) * D_ + d0 + tx] = l;
    }
}

// ---------------------------------------------------------------------------
// Kernel C: hpb[b,u] = h@W1 + b1 + b2
// ---------------------------------------------------------------------------
__global__ void hproj_kernel(const float* __restrict__ h,
                             const float* __restrict__ W1,
                             const float* __restrict__ b1,
                             const float* __restrict__ b2) {
    __shared__ float hs[D_];
    const int b = blockIdx.y;
    const int u = blockIdx.x * 256 + threadIdx.x;
    for (int i = threadIdx.x; i < D_; i += 256) hs[i] = h[b * D_ + i];
    __syncthreads();
    float acc = 0.f;
    #pragma unroll 8
    for (int d = 0; d < D_; d++) acc = fmaf(hs[d], W1[d * U_ + u], acc);
    g_hpb[b * U_ + u] = acc + b1[u] + b2[u];
}

// ---------------------------------------------------------------------------
// Kernel D: score GEMM via mma.sync (bf16, split-fp32, 3 products), fused
// tanh/V epilogue. CTA: 128 rows x 256 cols/pass, 4 passes; K chunks of 32,
// cp.async double-buffered; 8 warps at 64x64.
// Smem rows padded to 80B (5x16B) -> conflict-free ldmatrix.
// ---------------------------------------------------------------------------
#define ROWB     80                     // bytes per padded smem row (32 bf16 + 8 pad)
#define A_SPL    (128 * ROWB)           // 10240 per split
#define B_SPL    (256 * ROWB)           // 20480 per split
#define STAGE_SZ (2 * A_SPL + 2 * B_SPL)  // 61440
#define OFF_B    (2 * A_SPL)
#define OFF_VH   (2 * STAGE_SZ)         // 122880
#define OFF_RED  (OFF_VH + 2048)
#define SK_SMEM  (OFF_RED + 2048)       // 126976

__global__ void __launch_bounds__(256, 1)
score_kernel(const float* __restrict__ V) {
    extern __shared__ char smem[];
    const uint32_t sb = smem_u32(smem);
    const int tid = threadIdx.x;
    const int lane = tid & 31;
    const int wid = tid >> 5;
    const int warp_m = wid >> 2;        // 0..1  (64 rows each)
    const int warp_n = wid & 3;         // 0..3  (64 cols each)
    const int row0 = blockIdx.x * 128;
    const int b = row0 >> 12;

    float* vbuf = (float*)(smem + OFF_VH);
    float* hbuf = (float*)(smem + OFF_VH + 1024);
    float* red  = (float*)(smem + OFF_RED);

    // ldmatrix per-lane offsets
    const uint32_t a_loff = (uint32_t)((lane & 15) * ROWB + (lane >> 4) * 16);
    const uint32_t b_loff = (uint32_t)(((lane & 7) + ((lane >> 4) << 3)) * ROWB
                                       + ((lane >> 3) & 1) * 16);

    float rowsum8[8];
    #pragma unroll
    for (int j = 0; j < 8; j++) rowsum8[j] = 0.f;

    for (int np = 0; np < 4; np++) {
        const int n0 = np * 256;
        vbuf[tid] = V[n0 + tid];
        hbuf[tid] = g_hpb[b * U_ + n0 + tid];

        float acc[4][8][4];
        #pragma unroll
        for (int mt = 0; mt < 4; mt++)
            #pragma unroll
            for (int nt = 0; nt < 8; nt++)
                #pragma unroll
                for (int c = 0; c < 4; c++) acc[mt][nt][c] = 0.f;

        __syncthreads();   // vbuf/hbuf ready; previous pass fully done

        // ---- stage loader (K chunk of 32 into stage s) ----
        auto load_stage = [&](int s, int k0) {
            const uint32_t stg = sb + s * STAGE_SZ;
            // A: 2 splits x 128 rows x 4 16B-chunks = 1024 tasks
            #pragma unroll
            for (int it = 0; it < 4; it++) {
                const int task = tid + it * 256;
                const int spl = task >> 9;
                const int r   = (task >> 2) & 127;
                const int c   = task & 3;
                const __nv_bfloat16* src = (spl ? g_Xlo : g_Xhi)
                    + (size_t)(row0 + r) * D_ + k0 + c * 8;
                CP_ASYNC16(stg + spl * A_SPL + r * ROWB + c * 16, src);
            }
            // B: 2 splits x 256 rows x 4 chunks = 2048 tasks
            #pragma unroll
            for (int it = 0; it < 8; it++) {
                const int task = tid + it * 256;
                const int spl = task >> 10;
                const int r   = (task >> 2) & 255;
                const int c   = task & 3;
                const __nv_bfloat16* src = (spl ? g_Wlo : g_Whi)
                    + (size_t)(n0 + r) * D_ + k0 + c * 8;
                CP_ASYNC16(stg + OFF_B + spl * B_SPL + r * ROWB + c * 16, src);
            }
        };

        load_stage(0, 0);
        CP_COMMIT();

        #pragma unroll 1
        for (int kc = 0; kc < 32; kc++) {
            if (kc + 1 < 32) load_stage((kc + 1) & 1, (kc + 1) * 32);
            CP_COMMIT();
            CP_WAIT1();
            __syncthreads();

            const uint32_t stg = sb + (kc & 1) * STAGE_SZ;
            const uint32_t aBase = stg + warp_m * 64 * ROWB + a_loff;
            const uint32_t bBase = stg + OFF_B + warp_n * 64 * ROWB + b_loff;

            #pragma unroll
            for (int k16 = 0; k16 < 2; k16++) {
                const uint32_t ko = k16 * 32;
                uint32_t af[4][4], bh[4][4], bl[4][4];
                #pragma unroll
                for (int i = 0; i < 4; i++) {   // B hi + lo (each x4 = 2 n8-tiles)
                    ldm_x4(bh[i], bBase + i * 16 * ROWB + ko);
                    ldm_x4(bl[i], bBase + B_SPL + i * 16 * ROWB + ko);
                }
                #pragma unroll
                for (int mt = 0; mt < 4; mt++)  // A hi
                    ldm_x4(af[mt], aBase + mt * 16 * ROWB + ko);
                #pragma unroll
                for (int mt = 0; mt < 4; mt++)
                    #pragma unroll
                    for (int nt = 0; nt < 8; nt++) {
                        mma_bf16(acc[mt][nt], af[mt], &bh[nt >> 1][(nt & 1) * 2]); // hi*hi
                        mma_bf16(acc[mt][nt], af[mt], &bl[nt >> 1][(nt & 1) * 2]); // hi*lo
                    }
                #pragma unroll
                for (int mt = 0; mt < 4; mt++)  // A lo
                    ldm_x4(af[mt], aBase + A_SPL + mt * 16 * ROWB + ko);
                #pragma unroll
                for (int mt = 0; mt < 4; mt++)
                    #pragma unroll
                    for (int nt = 0; nt < 8; nt++)
                        mma_bf16(acc[mt][nt], af[mt], &bh[nt >> 1][(nt & 1) * 2]); // lo*hi
            }
            __syncthreads();
        }

        // ---- epilogue: fold tanh + V into per-row partials ----
        #pragma unroll
        for (int mt = 0; mt < 4; mt++)
            #pragma unroll
            for (int nt = 0; nt < 8; nt++)
                #pragma unroll
                for (int c = 0; c < 4; c++) {
                    const int ul = warp_n * 64 + nt * 8 + (lane & 3) * 2 + (c & 1);
                    const float s = acc[mt][nt][c] + hbuf[ul];
                    rowsum8[mt * 2 + (c >> 1)] =
                        fmaf(vbuf[ul], fast_tanh(s), rowsum8[mt * 2 + (c >> 1)]);
                }
        __syncthreads();   // protect vbuf/hbuf before next pass overwrites
    }

    // ---- cross-thread reduction ----
    #pragma unroll
    for (int j = 0; j < 8; j++) {
        float v = rowsum8[j];
        v += __shfl_xor_sync(0xffffffffu, v, 1);
        v += __shfl_xor_sync(0xffffffffu, v, 2);
        if ((lane & 3) == 0) {
            const int r = warp_m * 64 + (j >> 1) * 16 + (lane >> 2) + 8 * (j & 1);
            red[r * 4 + warp_n] = v;
        }
    }
    __syncthreads();
    if (tid < 128)
        g_score[row0 + tid] = red[tid * 4 + 0] + red[tid * 4 + 1]
                            + red[tid * 4 + 2] + red[tid * 4 + 3];
}

// ---------------------------------------------------------------------------
// Kernel E: softmax over T per batch (bv constant -> softmax-invariant)
// ---------------------------------------------------------------------------
__global__ void softmax_kernel(float* __restrict__ wout) {
    const int b = blockIdx.x;
    const float* s = g_score + b * T_;
    float* w = wout + b * T_;
    __shared__ float red[256];
    const int tid = threadIdx.x;

    float mx = -INFINITY;
    for (int t = tid; t < T_; t += 256) mx = fmaxf(mx, s[t]);
    red[tid] = mx; __syncthreads();
    for (int o = 128; o > 0; o >>= 1) {
        if (tid < o) red[tid] = fmaxf(red[tid], red[tid + o]);
        __syncthreads();
    }
    mx = red[0]; __syncthreads();

    float sum = 0.f;
    for (int t = tid; t < T_; t += 256) {
        const float e = expf(s[t] - mx);
        w[t] = e;
        sum += e;
    }
    red[tid] = sum; __syncthreads();
    for (int o = 128; o > 0; o >>= 1) {
        if (tid < o) red[tid] += red[tid + o];
        __syncthreads();
    }
    const float inv = 1.f / red[0];
    for (int t = tid; t < T_; t += 256) w[t] *= inv;
}

// ---------------------------------------------------------------------------
// Kernel F: context[b,d] = sum_t w[b,t] * enc[b,t,d]
// ---------------------------------------------------------------------------
__global__ void context_kernel(const float* __restrict__ enc,
                               const float* __restrict__ w,
                               float* __restrict__ ctx) {
    const int b  = blockIdx.y;
    const int t0 = blockIdx.x * 128;
    const int tid = threadIdx.x;
    float c[4] = {0.f, 0.f, 0.f, 0.f};
    for (int t = t0; t < t0 + 128; t++) {
        const float wt = w[b * T_ + t];
        const float* row = enc + ((size_t)b * T_ + t) * D_;
        #pragma unroll
        for (int j = 0; j < 4; j++)
            c[j] = fmaf(wt, row[tid + j * 256], c[j]);
    }
    #pragma unroll
    for (int j = 0; j < 4; j++)
        atomicAdd(&ctx[b * D_ + tid + j * 256], c[j]);
}

// ---------------------------------------------------------------------------
extern "C" void kernel_launch(void* const* d_in, const int* in_sizes, int n_in,
                              void* d_out, int out_size) {
    const float* h   = (const float*)d_in[0];  // [B, D]
    const float* enc = (const float*)d_in[1];  // [B, T, D]
    const float* W1  = (const float*)d_in[2];  // [D, U]
    const float* b1  = (const float*)d_in[3];  // [U]
    const float* W2  = (const float*)d_in[4];  // [D, U]
    const float* b2  = (const float*)d_in[5];  // [U]
    const float* V   = (const float*)d_in[6];  // [U, 1]
    // d_in[7] = bv: softmax-invariant constant, unused.

    float* out = (float*)d_out;
    float* ctx = out;             // [B, D]
    float* wts = out + B_ * D_;   // [B, T, 1]

    cudaFuncSetAttribute(score_kernel,
                         cudaFuncAttributeMaxDynamicSharedMemorySize, SK_SMEM);

    cudaMemsetAsync(ctx, 0, (size_t)B_ * D_ * sizeof(float));

    convert_x_kernel<<<(M_ * D_) / (256 * 8), 256>>>(enc);
    convert_w_kernel<<<dim3(32, 32), dim3(32, 8)>>>(W2);
    hproj_kernel<<<dim3(U_ / 256, B_), 256>>>(h, W1, b1, b2);
    score_kernel<<<M_ / 128, 256, SK_SMEM>>>(V);
    softmax_kernel<<<B_, 256>>>(wts);
    context_kernel<<<dim3(T_ / 128, B_), 256>>>(enc, wts, ctx);
}

// round 4
// speedup vs baseline: 2.3257x; 1.0065x over previous
#include <cuda_runtime.h>
#include <cuda_bf16.h>
#include <math.h>
#include <stdint.h>

// Problem constants
#define B_  16
#define T_  4096
#define D_  1024
#define U_  1024
#define M_  (B_ * T_)   // 65536 rows

// ---------------------------------------------------------------------------
// Device-global scratch (no allocations allowed)
// ---------------------------------------------------------------------------
__device__ __nv_bfloat16 g_Xhi[(size_t)M_ * D_];   // 128 MiB
__device__ __nv_bfloat16 g_Xlo[(size_t)M_ * D_];   // 128 MiB
__device__ __nv_bfloat16 g_Whi[(size_t)U_ * D_];   // W2^T [u][d]
__device__ __nv_bfloat16 g_Wlo[(size_t)U_ * D_];
__device__ float g_hpb[B_ * U_];
__device__ float g_score[M_];

// ---------------------------------------------------------------------------
// Helpers
// ---------------------------------------------------------------------------
__device__ __forceinline__ uint32_t smem_u32(const void* p) {
    uint32_t a;
    asm("{ .reg .u64 t; cvta.to.shared.u64 t, %1; cvt.u32.u64 %0, t; }" : "=r"(a) : "l"(p));
    return a;
}
#define CP_ASYNC16(dst, src) \
    asm volatile("cp.async.cg.shared.global [%0], [%1], 16;" :: "r"(dst), "l"(src))
#define CP_COMMIT() asm volatile("cp.async.commit_group;" ::: "memory")
#define CP_WAIT1()  asm volatile("cp.async.wait_group 1;" ::: "memory")

__device__ __forceinline__ void ldm_x4(uint32_t* r, uint32_t addr) {
    asm volatile("ldmatrix.sync.aligned.m8n8.x4.shared.b16 {%0,%1,%2,%3}, [%4];"
                 : "=r"(r[0]), "=r"(r[1]), "=r"(r[2]), "=r"(r[3]) : "r"(addr));
}
__device__ __forceinline__ void mma_bf16(float* c, const uint32_t* a, const uint32_t* b) {
    asm volatile(
        "mma.sync.aligned.m16n8k16.row.col.f32.bf16.bf16.f32 "
        "{%0,%1,%2,%3}, {%4,%5,%6,%7}, {%8,%9}, {%0,%1,%2,%3};"
        : "+f"(c[0]), "+f"(c[1]), "+f"(c[2]), "+f"(c[3])
        : "r"(a[0]), "r"(a[1]), "r"(a[2]), "r"(a[3]), "r"(b[0]), "r"(b[1]));
}

// FMA-only fast tanh (abs err ~1e-6); avoids MUFU entirely.
__device__ __forceinline__ float fast_tanh(float x) {
    float ax = fabsf(x);
    float t = fminf(ax * 2.885390082f, 30.0f);     // 2|x|*log2(e)
    float nt = -t;
    float fi = floorf(nt);
    float f = nt - fi;                              // [0,1)
    float p =              1.5253232e-5f;
    p = fmaf(p, f, 1.5403530e-4f);
    p = fmaf(p, f, 1.3333558e-3f);
    p = fmaf(p, f, 9.6181291e-3f);
    p = fmaf(p, f, 5.5504109e-2f);
    p = fmaf(p, f, 2.4022651e-1f);
    p = fmaf(p, f, 6.9314718e-1f);
    p = fmaf(p, f, 1.0f);
    int ei = (int)fi;                               // [-30, 0]
    float e = __int_as_float((ei + 127) << 23) * p; // 2^nt = e^{-2|x|}
    float d = 1.0f + e;
    float r = __int_as_float(0x7EF311C3u - __float_as_int(d));
    r = r * (2.0f - d * r);
    r = r * (2.0f - d * r);
    r = r * (2.0f - d * r);
    float y = (1.0f - e) * r;
    return copysignf(y, x);
}

// ---------------------------------------------------------------------------
// Kernel A: split enc fp32 -> bf16 hi/lo
// ---------------------------------------------------------------------------
__global__ void convert_x_kernel(const float* __restrict__ X) {
    size_t i = ((size_t)blockIdx.x * 256 + threadIdx.x) * 8;
    float4 a = *(const float4*)(X + i);
    float4 b = *(const float4*)(X + i + 4);
    float v[8] = {a.x, a.y, a.z, a.w, b.x, b.y, b.z, b.w};
    __nv_bfloat16 hi[8], lo[8];
    #pragma unroll
    for (int j = 0; j < 8; j++) {
        hi[j] = __float2bfloat16(v[j]);
        lo[j] = __float2bfloat16(v[j] - __bfloat162float(hi[j]));
    }
    *(uint4*)(g_Xhi + i) = *(uint4*)hi;
    *(uint4*)(g_Xlo + i) = *(uint4*)lo;
}

// ---------------------------------------------------------------------------
// Kernel B: transpose + split W2 [d][u] -> [u][d] bf16 hi/lo
// ---------------------------------------------------------------------------
__global__ void convert_w_kernel(const float* __restrict__ W2) {
    __shared__ float tile[32][33];
    const int u0 = blockIdx.x * 32, d0 = blockIdx.y * 32;
    const int tx = threadIdx.x, ty = threadIdx.y;           // (32, 8)
    #pragma unroll
    for (int j = 0; j < 32; j += 8)
        tile[ty + j][tx] = W2[(size_t)(d0 + ty + j) * U_ + u0 + tx];
    __syncthreads();
    #pragma unroll
    for (int j = 0; j < 32; j += 8) {
        float v = tile[tx][ty + j];
        __nv_bfloat16 h = __float2bfloat16(v);
        __nv_bfloat16 l = __float2bfloat16(v - __bfloat162float(h));
        g_Whi[(size_t)(u0 + ty + j) * D_ + d0 + tx] = h;
        g_Wlo[(size_t)(u0 + ty + j) * D_ + d0 + tx] = l;
    }
}

// ---------------------------------------------------------------------------
// Kernel C: hpb[b,u] = h@W1 + b1 + b2
// ---------------------------------------------------------------------------
__global__ void hproj_kernel(const float* __restrict__ h,
                             const float* __restrict__ W1,
                             const float* __restrict__ b1,
                             const float* __restrict__ b2) {
    __shared__ float hs[D_];
    const int b = blockIdx.y;
    const int u = blockIdx.x * 256 + threadIdx.x;
    for (int i = threadIdx.x; i < D_; i += 256) hs[i] = h[b * D_ + i];
    __syncthreads();
    float acc = 0.f;
    #pragma unroll 8
    for (int d = 0; d < D_; d++) acc = fmaf(hs[d], W1[d * U_ + u], acc);
    g_hpb[b * U_ + u] = acc + b1[u] + b2[u];
}

// ---------------------------------------------------------------------------
// Kernel D: score GEMM via mma.sync (bf16, split-fp32, 3 products), fused
// tanh/V epilogue. CTA: 128 rows x 256 cols/pass, 4 passes; K chunks of 32,
// THREE-stage cp.async pipeline, ONE barrier per chunk; 8 warps at 64x64.
// Smem rows padded to 80B (5x16B) -> conflict-free ldmatrix.
// ---------------------------------------------------------------------------
#define ROWB     80                       // bytes per padded smem row
#define A_SPL    (128 * ROWB)             // 10240 per split
#define B_SPL    (256 * ROWB)             // 20480 per split
#define STAGE_SZ (2 * A_SPL + 2 * B_SPL)  // 61440
#define OFF_B    (2 * A_SPL)
#define NSTAGE   3
#define OFF_VH   (NSTAGE * STAGE_SZ)      // 184320
#define OFF_RED  (OFF_VH + 2048)
#define SK_SMEM  (OFF_RED + 2048)         // 188416

__global__ void __launch_bounds__(256, 1)
score_kernel(const float* __restrict__ V) {
    extern __shared__ char smem[];
    const uint32_t sb = smem_u32(smem);
    const int tid = threadIdx.x;
    const int lane = tid & 31;
    const int wid = tid >> 5;
    const int warp_m = wid >> 2;        // 0..1  (64 rows each)
    const int warp_n = wid & 3;         // 0..3  (64 cols each)
    const int row0 = blockIdx.x * 128;
    const int b = row0 >> 12;

    float* vbuf = (float*)(smem + OFF_VH);
    float* hbuf = (float*)(smem + OFF_VH + 1024);
    float* red  = (float*)(smem + OFF_RED);

    const uint32_t a_loff = (uint32_t)((lane & 15) * ROWB + (lane >> 4) * 16);
    const uint32_t b_loff = (uint32_t)(((lane & 7) + ((lane >> 4) << 3)) * ROWB
                                       + ((lane >> 3) & 1) * 16);

    float rowsum8[8];
    #pragma unroll
    for (int j = 0; j < 8; j++) rowsum8[j] = 0.f;

    for (int np = 0; np < 4; np++) {
        const int n0 = np * 256;
        vbuf[tid] = V[n0 + tid];
        hbuf[tid] = g_hpb[b * U_ + n0 + tid];

        float acc[4][8][4];
        #pragma unroll
        for (int mt = 0; mt < 4; mt++)
            #pragma unroll
            for (int nt = 0; nt < 8; nt++)
                #pragma unroll
                for (int c = 0; c < 4; c++) acc[mt][nt][c] = 0.f;

        __syncthreads();   // vbuf/hbuf ready; all smem free (prev pass drained)

        // ---- stage loader (K chunk of 32 into stage s) ----
        auto load_stage = [&](int s, int k0) {
            const uint32_t stg = sb + s * STAGE_SZ;
            #pragma unroll
            for (int it = 0; it < 4; it++) {       // A: 1024 tasks
                const int task = tid + it * 256;
                const int spl = task >> 9;
                const int r   = (task >> 2) & 127;
                const int c   = task & 3;
                const __nv_bfloat16* src = (spl ? g_Xlo : g_Xhi)
                    + (size_t)(row0 + r) * D_ + k0 + c * 8;
                CP_ASYNC16(stg + spl * A_SPL + r * ROWB + c * 16, src);
            }
            #pragma unroll
            for (int it = 0; it < 8; it++) {       // B: 2048 tasks
                const int task = tid + it * 256;
                const int spl = task >> 10;
                const int r   = (task >> 2) & 255;
                const int c   = task & 3;
                const __nv_bfloat16* src = (spl ? g_Wlo : g_Whi)
                    + (size_t)(n0 + r) * D_ + k0 + c * 8;
                CP_ASYNC16(stg + OFF_B + spl * B_SPL + r * ROWB + c * 16, src);
            }
        };

        load_stage(0, 0);  CP_COMMIT();
        load_stage(1, 32); CP_COMMIT();

        #pragma unroll 1
        for (int kc = 0; kc < 32; kc++) {
            CP_WAIT1();           // stage kc has arrived (<=1 group pending)
            __syncthreads();      // data visible; all warps done with kc-1
            if (kc + 2 < 32) load_stage((kc + 2) % NSTAGE, (kc + 2) * 32);
            CP_COMMIT();          // always commit (keeps FIFO accounting)

            const uint32_t stg = sb + (kc % NSTAGE) * STAGE_SZ;
            const uint32_t aBase = stg + warp_m * 64 * ROWB + a_loff;
            const uint32_t bBase = stg + OFF_B + warp_n * 64 * ROWB + b_loff;

            #pragma unroll
            for (int k16 = 0; k16 < 2; k16++) {
                const uint32_t ko = k16 * 32;
                uint32_t af[4][4], bh[4][4], bl[4][4];
                #pragma unroll
                for (int i = 0; i < 4; i++) {
                    ldm_x4(bh[i], bBase + i * 16 * ROWB + ko);
                    ldm_x4(bl[i], bBase + B_SPL + i * 16 * ROWB + ko);
                }
                #pragma unroll
                for (int mt = 0; mt < 4; mt++)
                    ldm_x4(af[mt], aBase + mt * 16 * ROWB + ko);
                #pragma unroll
                for (int mt = 0; mt < 4; mt++)
                    #pragma unroll
                    for (int nt = 0; nt < 8; nt++) {
                        mma_bf16(acc[mt][nt], af[mt], &bh[nt >> 1][(nt & 1) * 2]); // hi*hi
                        mma_bf16(acc[mt][nt], af[mt], &bl[nt >> 1][(nt & 1) * 2]); // hi*lo
                    }
                #pragma unroll
                for (int mt = 0; mt < 4; mt++)
                    ldm_x4(af[mt], aBase + A_SPL + mt * 16 * ROWB + ko);
                #pragma unroll
                for (int mt = 0; mt < 4; mt++)
                    #pragma unroll
                    for (int nt = 0; nt < 8; nt++)
                        mma_bf16(acc[mt][nt], af[mt], &bh[nt >> 1][(nt & 1) * 2]); // lo*hi
            }
        }

        // ---- epilogue: fold tanh + V into per-row partials ----
        #pragma unroll
        for (int mt = 0; mt < 4; mt++)
            #pragma unroll
            for (int nt = 0; nt < 8; nt++)
                #pragma unroll
                for (int c = 0; c < 4; c++) {
                    const int ul = warp_n * 64 + nt * 8 + (lane & 3) * 2 + (c & 1);
                    const float s = acc[mt][nt][c] + hbuf[ul];
                    rowsum8[mt * 2 + (c >> 1)] =
                        fmaf(vbuf[ul], fast_tanh(s), rowsum8[mt * 2 + (c >> 1)]);
                }
        __syncthreads();   // protect vbuf/hbuf/stages before next pass
    }

    // ---- cross-thread reduction ----
    #pragma unroll
    for (int j = 0; j < 8; j++) {
        float v = rowsum8[j];
        v += __shfl_xor_sync(0xffffffffu, v, 1);
        v += __shfl_xor_sync(0xffffffffu, v, 2);
        if ((lane & 3) == 0) {
            const int r = warp_m * 64 + (j >> 1) * 16 + (lane >> 2) + 8 * (j & 1);
            red[r * 4 + warp_n] = v;
        }
    }
    __syncthreads();
    if (tid < 128)
        g_score[row0 + tid] = red[tid * 4 + 0] + red[tid * 4 + 1]
                            + red[tid * 4 + 2] + red[tid * 4 + 3];
}

// ---------------------------------------------------------------------------
// Kernel E: softmax over T per batch (bv constant -> softmax-invariant)
// ---------------------------------------------------------------------------
__global__ void softmax_kernel(float* __restrict__ wout) {
    const int b = blockIdx.x;
    const float* s = g_score + b * T_;
    float* w = wout + b * T_;
    __shared__ float red[256];
    const int tid = threadIdx.x;

    float mx = -INFINITY;
    for (int t = tid; t < T_; t += 256) mx = fmaxf(mx, s[t]);
    red[tid] = mx; __syncthreads();
    for (int o = 128; o > 0; o >>= 1) {
        if (tid < o) red[tid] = fmaxf(red[tid], red[tid + o]);
        __syncthreads();
    }
    mx = red[0]; __syncthreads();

    float sum = 0.f;
    for (int t = tid; t < T_; t += 256) {
        const float e = expf(s[t] - mx);
        w[t] = e;
        sum += e;
    }
    red[tid] = sum; __syncthreads();
    for (int o = 128; o > 0; o >>= 1) {
        if (tid < o) red[tid] += red[tid + o];
        __syncthreads();
    }
    const float inv = 1.f / red[0];
    for (int t = tid; t < T_; t += 256) w[t] *= inv;
}

// ---------------------------------------------------------------------------
// Kernel F: context[b,d] = sum_t w[b,t] * enc[b,t,d]
// ---------------------------------------------------------------------------
__global__ void context_kernel(const float* __restrict__ enc,
                               const float* __restrict__ w,
                               float* __restrict__ ctx) {
    const int b  = blockIdx.y;
    const int t0 = blockIdx.x * 128;
    const int tid = threadIdx.x;
    float c[4] = {0.f, 0.f, 0.f, 0.f};
    for (int t = t0; t < t0 + 128; t++) {
        const float wt = w[b * T_ + t];
        const float* row = enc + ((size_t)b * T_ + t) * D_;
        #pragma unroll
        for (int j = 0; j < 4; j++)
            c[j] = fmaf(wt, row[tid + j * 256], c[j]);
    }
    #pragma unroll
    for (int j = 0; j < 4; j++)
        atomicAdd(&ctx[b * D_ + tid + j * 256], c[j]);
}

// ---------------------------------------------------------------------------
extern "C" void kernel_launch(void* const* d_in, const int* in_sizes, int n_in,
                              void* d_out, int out_size) {
    const float* h   = (const float*)d_in[0];  // [B, D]
    const float* enc = (const float*)d_in[1];  // [B, T, D]
    const float* W1  = (const float*)d_in[2];  // [D, U]
    const float* b1  = (const float*)d_in[3];  // [U]
    const float* W2  = (const float*)d_in[4];  // [D, U]
    const float* b2  = (const float*)d_in[5];  // [U]
    const float* V   = (const float*)d_in[6];  // [U, 1]
    // d_in[7] = bv: softmax-invariant constant, unused.

    float* out = (float*)d_out;
    float* ctx = out;             // [B, D]
    float* wts = out + B_ * D_;   // [B, T, 1]

    cudaFuncSetAttribute(score_kernel,
                         cudaFuncAttributeMaxDynamicSharedMemorySize, SK_SMEM);

    cudaMemsetAsync(ctx, 0, (size_t)B_ * D_ * sizeof(float));

    convert_x_kernel<<<(M_ * D_) / (256 * 8), 256>>>(enc);
    convert_w_kernel<<<dim3(32, 32), dim3(32, 8)>>>(W2);
    hproj_kernel<<<dim3(U_ / 256, B_), 256>>>(h, W1, b1, b2);
    score_kernel<<<M_ / 128, 256, SK_SMEM>>>(V);
    softmax_kernel<<<B_, 256>>>(wts);
    context_kernel<<<dim3(T_ / 128, B_), 256>>>(enc, wts, ctx);
}

// round 5
// speedup vs baseline: 2.4375x; 1.0481x over previous
#include <cuda_runtime.h>
#include <cuda_bf16.h>
#include <math.h>
#include <stdint.h>

// Problem constants
#define B_  16
#define T_  4096
#define D_  1024
#define U_  1024
#define M_  (B_ * T_)   // 65536 rows

// ---------------------------------------------------------------------------
// Device-global scratch (no allocations allowed)
// ---------------------------------------------------------------------------
__device__ __nv_bfloat16 g_Xhi[(size_t)M_ * D_];   // 128 MiB
__device__ __nv_bfloat16 g_Xlo[(size_t)M_ * D_];   // 128 MiB
__device__ __nv_bfloat16 g_Whi[(size_t)U_ * D_];   // W2^T [u][d]
__device__ __nv_bfloat16 g_Wlo[(size_t)U_ * D_];
__device__ float g_hpb[B_ * U_];
__device__ float g_score[M_];

// ---------------------------------------------------------------------------
// Helpers
// ---------------------------------------------------------------------------
__device__ __forceinline__ uint32_t smem_u32(const void* p) {
    uint32_t a;
    asm("{ .reg .u64 t; cvta.to.shared.u64 t, %1; cvt.u32.u64 %0, t; }" : "=r"(a) : "l"(p));
    return a;
}
#define CP_ASYNC16(dst, src) \
    asm volatile("cp.async.cg.shared.global [%0], [%1], 16;" :: "r"(dst), "l"(src))
#define CP_COMMIT() asm volatile("cp.async.commit_group;" ::: "memory")
#define CP_WAIT1()  asm volatile("cp.async.wait_group 1;" ::: "memory")

__device__ __forceinline__ void ldm_x4(uint32_t* r, uint32_t addr) {
    asm volatile("ldmatrix.sync.aligned.m8n8.x4.shared.b16 {%0,%1,%2,%3}, [%4];"
                 : "=r"(r[0]), "=r"(r[1]), "=r"(r[2]), "=r"(r[3]) : "r"(addr));
}
__device__ __forceinline__ void mma_bf16(float* c, const uint32_t* a, const uint32_t* b) {
    asm volatile(
        "mma.sync.aligned.m16n8k16.row.col.f32.bf16.bf16.f32 "
        "{%0,%1,%2,%3}, {%4,%5,%6,%7}, {%8,%9}, {%0,%1,%2,%3};"
        : "+f"(c[0]), "+f"(c[1]), "+f"(c[2]), "+f"(c[3])
        : "r"(a[0]), "r"(a[1]), "r"(a[2]), "r"(a[3]), "r"(b[0]), "r"(b[1]));
}

// FMA-only fast tanh (abs err ~1e-6); avoids MUFU entirely.
__device__ __forceinline__ float fast_tanh(float x) {
    float ax = fabsf(x);
    float t = fminf(ax * 2.885390082f, 30.0f);     // 2|x|*log2(e)
    float nt = -t;
    float fi = floorf(nt);
    float f = nt - fi;                              // [0,1)
    float p =              1.5253232e-5f;
    p = fmaf(p, f, 1.5403530e-4f);
    p = fmaf(p, f, 1.3333558e-3f);
    p = fmaf(p, f, 9.6181291e-3f);
    p = fmaf(p, f, 5.5504109e-2f);
    p = fmaf(p, f, 2.4022651e-1f);
    p = fmaf(p, f, 6.9314718e-1f);
    p = fmaf(p, f, 1.0f);
    int ei = (int)fi;                               // [-30, 0]
    float e = __int_as_float((ei + 127) << 23) * p; // 2^nt = e^{-2|x|}
    float d = 1.0f + e;
    float r = __int_as_float(0x7EF311C3u - __float_as_int(d));
    r = r * (2.0f - d * r);
    r = r * (2.0f - d * r);
    r = r * (2.0f - d * r);
    float y = (1.0f - e) * r;
    return copysignf(y, x);
}

// ---------------------------------------------------------------------------
// Kernel A: split enc fp32 -> bf16 hi/lo
// ---------------------------------------------------------------------------
__global__ void convert_x_kernel(const float* __restrict__ X) {
    size_t i = ((size_t)blockIdx.x * 256 + threadIdx.x) * 8;
    float4 a = *(const float4*)(X + i);
    float4 b = *(const float4*)(X + i + 4);
    float v[8] = {a.x, a.y, a.z, a.w, b.x, b.y, b.z, b.w};
    __nv_bfloat16 hi[8], lo[8];
    #pragma unroll
    for (int j = 0; j < 8; j++) {
        hi[j] = __float2bfloat16(v[j]);
        lo[j] = __float2bfloat16(v[j] - __bfloat162float(hi[j]));
    }
    *(uint4*)(g_Xhi + i) = *(uint4*)hi;
    *(uint4*)(g_Xlo + i) = *(uint4*)lo;
}

// ---------------------------------------------------------------------------
// Kernel B: transpose + split W2 [d][u] -> [u][d] bf16 hi/lo
// ---------------------------------------------------------------------------
__global__ void convert_w_kernel(const float* __restrict__ W2) {
    __shared__ float tile[32][33];
    const int u0 = blockIdx.x * 32, d0 = blockIdx.y * 32;
    const int tx = threadIdx.x, ty = threadIdx.y;           // (32, 8)
    #pragma unroll
    for (int j = 0; j < 32; j += 8)
        tile[ty + j][tx] = W2[(size_t)(d0 + ty + j) * U_ + u0 + tx];
    __syncthreads();
    #pragma unroll
    for (int j = 0; j < 32; j += 8) {
        float v = tile[tx][ty + j];
        __nv_bfloat16 h = __float2bfloat16(v);
        __nv_bfloat16 l = __float2bfloat16(v - __bfloat162float(h));
        g_Whi[(size_t)(u0 + ty + j) * D_ + d0 + tx] = h;
        g_Wlo[(size_t)(u0 + ty + j) * D_ + d0 + tx] = l;
    }
}

// ---------------------------------------------------------------------------
// Kernel C: hpb[b,u] = h@W1 + b1 + b2
// ---------------------------------------------------------------------------
__global__ void hproj_kernel(const float* __restrict__ h,
                             const float* __restrict__ W1,
                             const float* __restrict__ b1,
                             const float* __restrict__ b2) {
    __shared__ float hs[D_];
    const int b = blockIdx.y;
    const int u = blockIdx.x * 256 + threadIdx.x;
    for (int i = threadIdx.x; i < D_; i += 256) hs[i] = h[b * D_ + i];
    __syncthreads();
    float acc = 0.f;
    #pragma unroll 8
    for (int d = 0; d < D_; d++) acc = fmaf(hs[d], W1[d * U_ + u], acc);
    g_hpb[b * U_ + u] = acc + b1[u] + b2[u];
}

// ---------------------------------------------------------------------------
// Kernel D: score GEMM via mma.sync (bf16, split-fp32, 3 products), fused
// tanh/V epilogue. CTA: 128 rows x 256 cols/pass, 4 passes; K chunks of 32,
// 3-stage cp.async pipeline, one barrier per chunk.
// 512 threads / 16 warps (4 per SMSP), warp tile 64x32, 64 acc regs/thread.
// MMA sweeps separated (hi*hi, hi*lo, lo*hi) -> 16-deep independent chains.
// ---------------------------------------------------------------------------
#define ROWB     80                       // bytes per padded smem row
#define A_SPL    (128 * ROWB)             // 10240 per split
#define B_SPL    (256 * ROWB)             // 20480 per split
#define STAGE_SZ (2 * A_SPL + 2 * B_SPL)  // 61440
#define OFF_B    (2 * A_SPL)
#define NSTAGE   3
#define OFF_VH   (NSTAGE * STAGE_SZ)      // 184320
#define OFF_RED  (OFF_VH + 2048)
#define SK_SMEM  (OFF_RED + 4096)         // 190464

__global__ void __launch_bounds__(512, 1)
score_kernel(const float* __restrict__ V) {
    extern __shared__ char smem[];
    const uint32_t sb = smem_u32(smem);
    const int tid = threadIdx.x;
    const int lane = tid & 31;
    const int wid = tid >> 5;
    const int warp_m = wid >> 3;        // 0..1  (64 rows each)
    const int warp_n = wid & 7;         // 0..7  (32 cols each)
    const int row0 = blockIdx.x * 128;
    const int b = row0 >> 12;

    float* vbuf = (float*)(smem + OFF_VH);
    float* hbuf = (float*)(smem + OFF_VH + 1024);
    float* red  = (float*)(smem + OFF_RED);

    const uint32_t a_loff = (uint32_t)((lane & 15) * ROWB + (lane >> 4) * 16);
    const uint32_t b_loff = (uint32_t)(((lane & 7) + ((lane >> 4) << 3)) * ROWB
                                       + ((lane >> 3) & 1) * 16);

    float rowsum8[8];
    #pragma unroll
    for (int j = 0; j < 8; j++) rowsum8[j] = 0.f;

    for (int np = 0; np < 4; np++) {
        const int n0 = np * 256;
        if (tid < 256) {
            vbuf[tid] = V[n0 + tid];
            hbuf[tid] = g_hpb[b * U_ + n0 + tid];
        }

        float acc[4][4][4];                // 64 regs: 4 m16 x 4 n8 x 4
        #pragma unroll
        for (int mt = 0; mt < 4; mt++)
            #pragma unroll
            for (int nt = 0; nt < 4; nt++)
                #pragma unroll
                for (int c = 0; c < 4; c++) acc[mt][nt][c] = 0.f;

        __syncthreads();   // vbuf/hbuf ready; all smem free

        // ---- stage loader (K chunk of 32 into stage s), 512 threads ----
        auto load_stage = [&](int s, int k0) {
            const uint32_t stg = sb + s * STAGE_SZ;
            #pragma unroll
            for (int it = 0; it < 2; it++) {       // A: 1024 tasks
                const int task = tid + it * 512;
                const int spl = task >> 9;
                const int r   = (task >> 2) & 127;
                const int c   = task & 3;
                const __nv_bfloat16* src = (spl ? g_Xlo : g_Xhi)
                    + (size_t)(row0 + r) * D_ + k0 + c * 8;
                CP_ASYNC16(stg + spl * A_SPL + r * ROWB + c * 16, src);
            }
            #pragma unroll
            for (int it = 0; it < 4; it++) {       // B: 2048 tasks
                const int task = tid + it * 512;
                const int spl = task >> 10;
                const int r   = (task >> 2) & 255;
                const int c   = task & 3;
                const __nv_bfloat16* src = (spl ? g_Wlo : g_Whi)
                    + (size_t)(n0 + r) * D_ + k0 + c * 8;
                CP_ASYNC16(stg + OFF_B + spl * B_SPL + r * ROWB + c * 16, src);
            }
        };

        load_stage(0, 0);  CP_COMMIT();
        load_stage(1, 32); CP_COMMIT();

        #pragma unroll 1
        for (int kc = 0; kc < 32; kc++) {
            CP_WAIT1();
            __syncthreads();
            if (kc + 2 < 32) load_stage((kc + 2) % NSTAGE, (kc + 2) * 32);
            CP_COMMIT();

            const uint32_t stg = sb + (kc % NSTAGE) * STAGE_SZ;
            const uint32_t aBase = stg + warp_m * 64 * ROWB + a_loff;
            const uint32_t bBase = stg + OFF_B + warp_n * 32 * ROWB + b_loff;

            #pragma unroll
            for (int k16 = 0; k16 < 2; k16++) {
                const uint32_t ko = k16 * 32;
                uint32_t af[4][4], bh[2][4], bl[2][4];
                #pragma unroll
                for (int i = 0; i < 2; i++) {      // B: 32 cols hi + lo
                    ldm_x4(bh[i], bBase + i * 16 * ROWB + ko);
                    ldm_x4(bl[i], bBase + B_SPL + i * 16 * ROWB + ko);
                }
                #pragma unroll
                for (int mt = 0; mt < 4; mt++)     // A hi: 64 rows
                    ldm_x4(af[mt], aBase + mt * 16 * ROWB + ko);
                // sweep 1: hi*hi (16 independent MMAs)
                #pragma unroll
                for (int mt = 0; mt < 4; mt++)
                    #pragma unroll
                    for (int nt = 0; nt < 4; nt++)
                        mma_bf16(acc[mt][nt], af[mt], &bh[nt >> 1][(nt & 1) * 2]);
                // sweep 2: hi*lo
                #pragma unroll
                for (int mt = 0; mt < 4; mt++)
                    #pragma unroll
                    for (int nt = 0; nt < 4; nt++)
                        mma_bf16(acc[mt][nt], af[mt], &bl[nt >> 1][(nt & 1) * 2]);
                #pragma unroll
                for (int mt = 0; mt < 4; mt++)     // A lo
                    ldm_x4(af[mt], aBase + A_SPL + mt * 16 * ROWB + ko);
                // sweep 3: lo*hi
                #pragma unroll
                for (int mt = 0; mt < 4; mt++)
                    #pragma unroll
                    for (int nt = 0; nt < 4; nt++)
                        mma_bf16(acc[mt][nt], af[mt], &bh[nt >> 1][(nt & 1) * 2]);
            }
        }

        // ---- epilogue: fold tanh + V into per-row partials ----
        #pragma unroll
        for (int mt = 0; mt < 4; mt++)
            #pragma unroll
            for (int nt = 0; nt < 4; nt++)
                #pragma unroll
                for (int c = 0; c < 4; c++) {
                    const int ul = warp_n * 32 + nt * 8 + (lane & 3) * 2 + (c & 1);
                    const float s = acc[mt][nt][c] + hbuf[ul];
                    rowsum8[mt * 2 + (c >> 1)] =
                        fmaf(vbuf[ul], fast_tanh(s), rowsum8[mt * 2 + (c >> 1)]);
                }
        __syncthreads();   // protect vbuf/hbuf/stages before next pass
    }

    // ---- cross-thread reduction ----
    // rowsum8[j] (j = mt*2 + chalf) lives at row = warp_m*64 + mt*16 +
    // (lane>>2) + 8*chalf, replicated over lane&3; 8 warp_n slices sum in smem.
    #pragma unroll
    for (int j = 0; j < 8; j++) {
        float v = rowsum8[j];
        v += __shfl_xor_sync(0xffffffffu, v, 1);
        v += __shfl_xor_sync(0xffffffffu, v, 2);
        if ((lane & 3) == 0) {
            const int r = warp_m * 64 + (j >> 1) * 16 + (lane >> 2) + 8 * (j & 1);
            red[r * 8 + warp_n] = v;
        }
    }
    __syncthreads();
    if (tid < 128) {
        float s = 0.f;
        #pragma unroll
        for (int j = 0; j < 8; j++) s += red[tid * 8 + j];
        g_score[row0 + tid] = s;
    }
}

// ---------------------------------------------------------------------------
// Kernel E: softmax over T per batch (bv constant -> softmax-invariant)
// ---------------------------------------------------------------------------
__global__ void softmax_kernel(float* __restrict__ wout) {
    const int b = blockIdx.x;
    const float* s = g_score + b * T_;
    float* w = wout + b * T_;
    __shared__ float red[256];
    const int tid = threadIdx.x;

    float mx = -INFINITY;
    for (int t = tid; t < T_; t += 256) mx = fmaxf(mx, s[t]);
    red[tid] = mx; __syncthreads();
    for (int o = 128; o > 0; o >>= 1) {
        if (tid < o) red[tid] = fmaxf(red[tid], red[tid + o]);
        __syncthreads();
    }
    mx = red[0]; __syncthreads();

    float sum = 0.f;
    for (int t = tid; t < T_; t += 256) {
        const float e = expf(s[t] - mx);
        w[t] = e;
        sum += e;
    }
    red[tid] = sum; __syncthreads();
    for (int o = 128; o > 0; o >>= 1) {
        if (tid < o) red[tid] += red[tid + o];
        __syncthreads();
    }
    const float inv = 1.f / red[0];
    for (int t = tid; t < T_; t += 256) w[t] *= inv;
}

// ---------------------------------------------------------------------------
// Kernel F: context[b,d] = sum_t w[b,t] * enc[b,t,d]
// ---------------------------------------------------------------------------
__global__ void context_kernel(const float* __restrict__ enc,
                               const float* __restrict__ w,
                               float* __restrict__ ctx) {
    const int b  = blockIdx.y;
    const int t0 = blockIdx.x * 128;
    const int tid = threadIdx.x;
    float c[4] = {0.f, 0.f, 0.f, 0.f};
    for (int t = t0; t < t0 + 128; t++) {
        const float wt = w[b * T_ + t];
        const float* row = enc + ((size_t)b * T_ + t) * D_;
        #pragma unroll
        for (int j = 0; j < 4; j++)
            c[j] = fmaf(wt, row[tid + j * 256], c[j]);
    }
    #pragma unroll
    for (int j = 0; j < 4; j++)
        atomicAdd(&ctx[b * D_ + tid + j * 256], c[j]);
}

// ---------------------------------------------------------------------------
extern "C" void kernel_launch(void* const* d_in, const int* in_sizes, int n_in,
                              void* d_out, int out_size) {
    const float* h   = (const float*)d_in[0];  // [B, D]
    const float* enc = (const float*)d_in[1];  // [B, T, D]
    const float* W1  = (const float*)d_in[2];  // [D, U]
    const float* b1  = (const float*)d_in[3];  // [U]
    const float* W2  = (const float*)d_in[4];  // [D, U]
    const float* b2  = (const float*)d_in[5];  // [U]
    const float* V   = (const float*)d_in[6];  // [U, 1]
    // d_in[7] = bv: softmax-invariant constant, unused.

    float* out = (float*)d_out;
    float* ctx = out;             // [B, D]
    float* wts = out + B_ * D_;   // [B, T, 1]

    cudaFuncSetAttribute(score_kernel,
                         cudaFuncAttributeMaxDynamicSharedMemorySize, SK_SMEM);

    cudaMemsetAsync(ctx, 0, (size_t)B_ * D_ * sizeof(float));

    convert_x_kernel<<<(M_ * D_) / (256 * 8), 256>>>(enc);
    convert_w_kernel<<<dim3(32, 32), dim3(32, 8)>>>(W2);
    hproj_kernel<<<dim3(U_ / 256, B_), 256>>>(h, W1, b1, b2);
    score_kernel<<<M_ / 128, 512, SK_SMEM>>>(V);
    softmax_kernel<<<B_, 256>>>(wts);
    context_kernel<<<dim3(T_ / 128, B_), 256>>>(enc, wts, ctx);
}

// round 6
// speedup vs baseline: 2.6158x; 1.0731x over previous
#include <cuda_runtime.h>
#include <cuda_bf16.h>
#include <math.h>
#include <stdint.h>

// Problem constants
#define B_  16
#define T_  4096
#define D_  1024
#define U_  1024
#define M_  (B_ * T_)   // 65536 rows

// ---------------------------------------------------------------------------
// Device-global scratch (no allocations allowed)
// ---------------------------------------------------------------------------
__device__ __nv_bfloat16 g_Xhi[(size_t)M_ * D_];   // 128 MiB
__device__ __nv_bfloat16 g_Xlo[(size_t)M_ * D_];   // 128 MiB
__device__ __nv_bfloat16 g_Whi[(size_t)U_ * D_];   // W2^T [u][d]
__device__ __nv_bfloat16 g_Wlo[(size_t)U_ * D_];
__device__ float g_hpb[B_ * U_];
__device__ float g_score[M_];

// ---------------------------------------------------------------------------
// Helpers
// ---------------------------------------------------------------------------
__device__ __forceinline__ uint32_t smem_u32(const void* p) {
    uint32_t a;
    asm("{ .reg .u64 t; cvta.to.shared.u64 t, %1; cvt.u32.u64 %0, t; }" : "=r"(a) : "l"(p));
    return a;
}
#define CP_ASYNC16(dst, src) \
    asm volatile("cp.async.cg.shared.global [%0], [%1], 16;" :: "r"(dst), "l"(src))
#define CP_COMMIT() asm volatile("cp.async.commit_group;" ::: "memory")
#define CP_WAIT1()  asm volatile("cp.async.wait_group 1;" ::: "memory")

__device__ __forceinline__ void ldm_x4(uint32_t* r, uint32_t addr) {
    asm volatile("ldmatrix.sync.aligned.m8n8.x4.shared.b16 {%0,%1,%2,%3}, [%4];"
                 : "=r"(r[0]), "=r"(r[1]), "=r"(r[2]), "=r"(r[3]) : "r"(addr));
}
__device__ __forceinline__ void mma_bf16(float* c, const uint32_t* a, const uint32_t* b) {
    asm volatile(
        "mma.sync.aligned.m16n8k16.row.col.f32.bf16.bf16.f32 "
        "{%0,%1,%2,%3}, {%4,%5,%6,%7}, {%8,%9}, {%0,%1,%2,%3};"
        : "+f"(c[0]), "+f"(c[1]), "+f"(c[2]), "+f"(c[3])
        : "r"(a[0]), "r"(a[1]), "r"(a[2]), "r"(a[3]), "r"(b[0]), "r"(b[1]));
}

// FMA-only fast tanh (abs err ~1e-6); avoids MUFU entirely.
__device__ __forceinline__ float fast_tanh(float x) {
    float ax = fabsf(x);
    float t = fminf(ax * 2.885390082f, 30.0f);     // 2|x|*log2(e)
    float nt = -t;
    float fi = floorf(nt);
    float f = nt - fi;                              // [0,1)
    float p =              1.5253232e-5f;
    p = fmaf(p, f, 1.5403530e-4f);
    p = fmaf(p, f, 1.3333558e-3f);
    p = fmaf(p, f, 9.6181291e-3f);
    p = fmaf(p, f, 5.5504109e-2f);
    p = fmaf(p, f, 2.4022651e-1f);
    p = fmaf(p, f, 6.9314718e-1f);
    p = fmaf(p, f, 1.0f);
    int ei = (int)fi;                               // [-30, 0]
    float e = __int_as_float((ei + 127) << 23) * p; // 2^nt = e^{-2|x|}
    float d = 1.0f + e;
    float r = __int_as_float(0x7EF311C3u - __float_as_int(d));
    r = r * (2.0f - d * r);
    r = r * (2.0f - d * r);
    r = r * (2.0f - d * r);
    float y = (1.0f - e) * r;
    return copysignf(y, x);
}

// ---------------------------------------------------------------------------
// Kernel A: split enc fp32 -> bf16 hi/lo
// ---------------------------------------------------------------------------
__global__ void convert_x_kernel(const float* __restrict__ X) {
    size_t i = ((size_t)blockIdx.x * 256 + threadIdx.x) * 8;
    float4 a = *(const float4*)(X + i);
    float4 b = *(const float4*)(X + i + 4);
    float v[8] = {a.x, a.y, a.z, a.w, b.x, b.y, b.z, b.w};
    __nv_bfloat16 hi[8], lo[8];
    #pragma unroll
    for (int j = 0; j < 8; j++) {
        hi[j] = __float2bfloat16(v[j]);
        lo[j] = __float2bfloat16(v[j] - __bfloat162float(hi[j]));
    }
    *(uint4*)(g_Xhi + i) = *(uint4*)hi;
    *(uint4*)(g_Xlo + i) = *(uint4*)lo;
}

// ---------------------------------------------------------------------------
// Kernel B: transpose + split W2 [d][u] -> [u][d] bf16 hi/lo
// ---------------------------------------------------------------------------
__global__ void convert_w_kernel(const float* __restrict__ W2) {
    __shared__ float tile[32][33];
    const int u0 = blockIdx.x * 32, d0 = blockIdx.y * 32;
    const int tx = threadIdx.x, ty = threadIdx.y;           // (32, 8)
    #pragma unroll
    for (int j = 0; j < 32; j += 8)
        tile[ty + j][tx] = W2[(size_t)(d0 + ty + j) * U_ + u0 + tx];
    __syncthreads();
    #pragma unroll
    for (int j = 0; j < 32; j += 8) {
        float v = tile[tx][ty + j];
        __nv_bfloat16 h = __float2bfloat16(v);
        __nv_bfloat16 l = __float2bfloat16(v - __bfloat162float(h));
        g_Whi[(size_t)(u0 + ty + j) * D_ + d0 + tx] = h;
        g_Wlo[(size_t)(u0 + ty + j) * D_ + d0 + tx] = l;
    }
}

// ---------------------------------------------------------------------------
// Kernel C: hpb[b,u] = h@W1 + b1 + b2
// ---------------------------------------------------------------------------
__global__ void hproj_kernel(const float* __restrict__ h,
                             const float* __restrict__ W1,
                             const float* __restrict__ b1,
                             const float* __restrict__ b2) {
    __shared__ float hs[D_];
    const int b = blockIdx.y;
    const int u = blockIdx.x * 256 + threadIdx.x;
    for (int i = threadIdx.x; i < D_; i += 256) hs[i] = h[b * D_ + i];
    __syncthreads();
    float acc = 0.f;
    #pragma unroll 8
    for (int d = 0; d < D_; d++) acc = fmaf(hs[d], W1[d * U_ + u], acc);
    g_hpb[b * U_ + u] = acc + b1[u] + b2[u];
}

// ---------------------------------------------------------------------------
// Kernel D: score GEMM via mma.sync (bf16, split-fp32, 3 products), fused
// tanh/V epilogue. Grid = 2048: each CTA owns one (128-row block, 256-col
// pass) pair -> 13.8 waves, ~1% tail. Partial row sums atomicAdd'ed to
// g_score. 3-stage cp.async pipeline, 512 threads / 16 warps, 64x32 warp
// tiles. All 12 LDSMs of a k16 issued up front (A hi/lo in separate regs).
// ---------------------------------------------------------------------------
#define ROWB     80                       // bytes per padded smem row
#define A_SPL    (128 * ROWB)             // 10240 per split
#define B_SPL    (256 * ROWB)             // 20480 per split
#define STAGE_SZ (2 * A_SPL + 2 * B_SPL)  // 61440
#define OFF_B    (2 * A_SPL)
#define NSTAGE   3
#define OFF_VH   (NSTAGE * STAGE_SZ)      // 184320
#define OFF_RED  (OFF_VH + 2048)
#define SK_SMEM  (OFF_RED + 4096)         // 190464

__global__ void __launch_bounds__(512, 1)
score_kernel(const float* __restrict__ V) {
    extern __shared__ char smem[];
    const uint32_t sb = smem_u32(smem);
    const int tid = threadIdx.x;
    const int lane = tid & 31;
    const int wid = tid >> 5;
    const int warp_m = wid >> 3;        // 0..1  (64 rows each)
    const int warp_n = wid & 7;         // 0..7  (32 cols each)
    const int row0 = (blockIdx.x >> 2) * 128;   // row block
    const int n0   = (blockIdx.x & 3) * 256;    // u-pass
    const int b = row0 >> 12;

    float* vbuf = (float*)(smem + OFF_VH);
    float* hbuf = (float*)(smem + OFF_VH + 1024);
    float* red  = (float*)(smem + OFF_RED);

    const uint32_t a_loff = (uint32_t)((lane & 15) * ROWB + (lane >> 4) * 16);
    const uint32_t b_loff = (uint32_t)(((lane & 7) + ((lane >> 4) << 3)) * ROWB
                                       + ((lane >> 3) & 1) * 16);

    if (tid < 256) {
        vbuf[tid] = V[n0 + tid];
        hbuf[tid] = g_hpb[b * U_ + n0 + tid];
    }

    float acc[4][4][4];                // 64 regs: 4 m16 x 4 n8 x 4
    #pragma unroll
    for (int mt = 0; mt < 4; mt++)
        #pragma unroll
        for (int nt = 0; nt < 4; nt++)
            #pragma unroll
            for (int c = 0; c < 4; c++) acc[mt][nt][c] = 0.f;

    // ---- stage loader (K chunk of 32 into stage s), 512 threads ----
    auto load_stage = [&](int s, int k0) {
        const uint32_t stg = sb + s * STAGE_SZ;
        #pragma unroll
        for (int it = 0; it < 2; it++) {       // A: 1024 tasks
            const int task = tid + it * 512;
            const int spl = task >> 9;
            const int r   = (task >> 2) & 127;
            const int c   = task & 3;
            const __nv_bfloat16* src = (spl ? g_Xlo : g_Xhi)
                + (size_t)(row0 + r) * D_ + k0 + c * 8;
            CP_ASYNC16(stg + spl * A_SPL + r * ROWB + c * 16, src);
        }
        #pragma unroll
        for (int it = 0; it < 4; it++) {       // B: 2048 tasks
            const int task = tid + it * 512;
            const int spl = task >> 10;
            const int r   = (task >> 2) & 255;
            const int c   = task & 3;
            const __nv_bfloat16* src = (spl ? g_Wlo : g_Whi)
                + (size_t)(n0 + r) * D_ + k0 + c * 8;
            CP_ASYNC16(stg + OFF_B + spl * B_SPL + r * ROWB + c * 16, src);
        }
    };

    load_stage(0, 0);  CP_COMMIT();
    load_stage(1, 32); CP_COMMIT();

    #pragma unroll 1
    for (int kc = 0; kc < 32; kc++) {
        CP_WAIT1();
        __syncthreads();
        if (kc + 2 < 32) load_stage((kc + 2) % NSTAGE, (kc + 2) * 32);
        CP_COMMIT();

        const uint32_t stg = sb + (kc % NSTAGE) * STAGE_SZ;
        const uint32_t aBase = stg + warp_m * 64 * ROWB + a_loff;
        const uint32_t bBase = stg + OFF_B + warp_n * 32 * ROWB + b_loff;

        #pragma unroll
        for (int k16 = 0; k16 < 2; k16++) {
            const uint32_t ko = k16 * 32;
            uint32_t afh[4][4], afl[4][4], bh[2][4], bl[2][4];
            // all 12 LDSMs up front -> MMAs stream without mid-sweep loads
            #pragma unroll
            for (int i = 0; i < 2; i++) {
                ldm_x4(bh[i], bBase + i * 16 * ROWB + ko);
                ldm_x4(bl[i], bBase + B_SPL + i * 16 * ROWB + ko);
            }
            #pragma unroll
            for (int mt = 0; mt < 4; mt++)
                ldm_x4(afh[mt], aBase + mt * 16 * ROWB + ko);
            #pragma unroll
            for (int mt = 0; mt < 4; mt++)
                ldm_x4(afl[mt], aBase + A_SPL + mt * 16 * ROWB + ko);
            // sweep 1: hi*hi
            #pragma unroll
            for (int mt = 0; mt < 4; mt++)
                #pragma unroll
                for (int nt = 0; nt < 4; nt++)
                    mma_bf16(acc[mt][nt], afh[mt], &bh[nt >> 1][(nt & 1) * 2]);
            // sweep 2: hi*lo
            #pragma unroll
            for (int mt = 0; mt < 4; mt++)
                #pragma unroll
                for (int nt = 0; nt < 4; nt++)
                    mma_bf16(acc[mt][nt], afh[mt], &bl[nt >> 1][(nt & 1) * 2]);
            // sweep 3: lo*hi
            #pragma unroll
            for (int mt = 0; mt < 4; mt++)
                #pragma unroll
                for (int nt = 0; nt < 4; nt++)
                    mma_bf16(acc[mt][nt], afl[mt], &bh[nt >> 1][(nt & 1) * 2]);
        }
    }

    // ---- epilogue: fold tanh + V into per-row partials ----
    float rowsum8[8];
    #pragma unroll
    for (int j = 0; j < 8; j++) rowsum8[j] = 0.f;
    #pragma unroll
    for (int mt = 0; mt < 4; mt++)
        #pragma unroll
        for (int nt = 0; nt < 4; nt++)
            #pragma unroll
            for (int c = 0; c < 4; c++) {
                const int ul = warp_n * 32 + nt * 8 + (lane & 3) * 2 + (c & 1);
                const float s = acc[mt][nt][c] + hbuf[ul];
                rowsum8[mt * 2 + (c >> 1)] =
                    fmaf(vbuf[ul], fast_tanh(s), rowsum8[mt * 2 + (c >> 1)]);
            }

    // cross-thread reduction: quad-shfl, then 8 warp_n slices via smem
    #pragma unroll
    for (int j = 0; j < 8; j++) {
        float v = rowsum8[j];
        v += __shfl_xor_sync(0xffffffffu, v, 1);
        v += __shfl_xor_sync(0xffffffffu, v, 2);
        if ((lane & 3) == 0) {
            const int r = warp_m * 64 + (j >> 1) * 16 + (lane >> 2) + 8 * (j & 1);
            red[r * 8 + warp_n] = v;
        }
    }
    __syncthreads();
    if (tid < 128) {
        float s = 0.f;
        #pragma unroll
        for (int j = 0; j < 8; j++) s += red[tid * 8 + j];
        atomicAdd(&g_score[row0 + tid], s);   // partial over this u-pass
    }
}

// ---------------------------------------------------------------------------
// Kernel E: softmax over T per batch (bv constant -> softmax-invariant)
// ---------------------------------------------------------------------------
__global__ void softmax_kernel(float* __restrict__ wout) {
    const int b = blockIdx.x;
    const float* s = g_score + b * T_;
    float* w = wout + b * T_;
    __shared__ float red[256];
    const int tid = threadIdx.x;

    float mx = -INFINITY;
    for (int t = tid; t < T_; t += 256) mx = fmaxf(mx, s[t]);
    red[tid] = mx; __syncthreads();
    for (int o = 128; o > 0; o >>= 1) {
        if (tid < o) red[tid] = fmaxf(red[tid], red[tid + o]);
        __syncthreads();
    }
    mx = red[0]; __syncthreads();

    float sum = 0.f;
    for (int t = tid; t < T_; t += 256) {
        const float e = expf(s[t] - mx);
        w[t] = e;
        sum += e;
    }
    red[tid] = sum; __syncthreads();
    for (int o = 128; o > 0; o >>= 1) {
        if (tid < o) red[tid] += red[tid + o];
        __syncthreads();
    }
    const float inv = 1.f / red[0];
    for (int t = tid; t < T_; t += 256) w[t] *= inv;
}

// ---------------------------------------------------------------------------
// Kernel F: context[b,d] = sum_t w[b,t] * enc[b,t,d]
// ---------------------------------------------------------------------------
__global__ void context_kernel(const float* __restrict__ enc,
                               const float* __restrict__ w,
                               float* __restrict__ ctx) {
    const int b  = blockIdx.y;
    const int t0 = blockIdx.x * 128;
    const int tid = threadIdx.x;
    float c[4] = {0.f, 0.f, 0.f, 0.f};
    for (int t = t0; t < t0 + 128; t++) {
        const float wt = w[b * T_ + t];
        const float* row = enc + ((size_t)b * T_ + t) * D_;
        #pragma unroll
        for (int j = 0; j < 4; j++)
            c[j] = fmaf(wt, row[tid + j * 256], c[j]);
    }
    #pragma unroll
    for (int j = 0; j < 4; j++)
        atomicAdd(&ctx[b * D_ + tid + j * 256], c[j]);
}

// ---------------------------------------------------------------------------
extern "C" void kernel_launch(void* const* d_in, const int* in_sizes, int n_in,
                              void* d_out, int out_size) {
    const float* h   = (const float*)d_in[0];  // [B, D]
    const float* enc = (const float*)d_in[1];  // [B, T, D]
    const float* W1  = (const float*)d_in[2];  // [D, U]
    const float* b1  = (const float*)d_in[3];  // [U]
    const float* W2  = (const float*)d_in[4];  // [D, U]
    const float* b2  = (const float*)d_in[5];  // [U]
    const float* V   = (const float*)d_in[6];  // [U, 1]
    // d_in[7] = bv: softmax-invariant constant, unused.

    float* out = (float*)d_out;
    float* ctx = out;             // [B, D]
    float* wts = out + B_ * D_;   // [B, T, 1]

    cudaFuncSetAttribute(score_kernel,
                         cudaFuncAttributeMaxDynamicSharedMemorySize, SK_SMEM);

    void* scorePtr = nullptr;
    cudaGetSymbolAddress(&scorePtr, g_score);

    cudaMemsetAsync(ctx, 0, (size_t)B_ * D_ * sizeof(float));
    cudaMemsetAsync(scorePtr, 0, (size_t)M_ * sizeof(float));

    convert_x_kernel<<<(M_ * D_) / (256 * 8), 256>>>(enc);
    convert_w_kernel<<<dim3(32, 32), dim3(32, 8)>>>(W2);
    hproj_kernel<<<dim3(U_ / 256, B_), 256>>>(h, W1, b1, b2);
    score_kernel<<<4 * (M_ / 128), 512, SK_SMEM>>>(V);
    softmax_kernel<<<B_, 256>>>(wts);
    context_kernel<<<dim3(T_ / 128, B_), 256>>>(enc, wts, ctx);
}

// round 7
// speedup vs baseline: 3.4984x; 1.3374x over previous
#include <cuda_runtime.h>
#include <cuda_fp16.h>
#include <math.h>
#include <stdint.h>

// Problem constants
#define B_  16
#define T_  4096
#define D_  1024
#define U_  1024
#define M_  (B_ * T_)   // 65536 rows

// ---------------------------------------------------------------------------
// Device-global scratch (no allocations allowed)
// ---------------------------------------------------------------------------
__device__ __half g_Xhi[(size_t)M_ * D_];   // 128 MiB  (fp16 hi of enc)
__device__ __half g_Whi[(size_t)U_ * D_];   // W2^T [u][d] hi
__device__ __half g_Wlo[(size_t)U_ * D_];   // W2^T [u][d] lo
__device__ float g_hpb[B_ * U_];
__device__ float g_score[M_];

// ---------------------------------------------------------------------------
// Helpers
// ---------------------------------------------------------------------------
__device__ __forceinline__ uint32_t smem_u32(const void* p) {
    uint32_t a;
    asm("{ .reg .u64 t; cvta.to.shared.u64 t, %1; cvt.u32.u64 %0, t; }" : "=r"(a) : "l"(p));
    return a;
}
#define CP_ASYNC16(dst, src) \
    asm volatile("cp.async.cg.shared.global [%0], [%1], 16;" :: "r"(dst), "l"(src))
#define CP_COMMIT() asm volatile("cp.async.commit_group;" ::: "memory")
#define CP_WAIT1()  asm volatile("cp.async.wait_group 1;" ::: "memory")

__device__ __forceinline__ void ldm_x4(uint32_t* r, uint32_t addr) {
    asm volatile("ldmatrix.sync.aligned.m8n8.x4.shared.b16 {%0,%1,%2,%3}, [%4];"
                 : "=r"(r[0]), "=r"(r[1]), "=r"(r[2]), "=r"(r[3]) : "r"(addr));
}
__device__ __forceinline__ void mma_fp16(float* c, const uint32_t* a, const uint32_t* b) {
    asm volatile(
        "mma.sync.aligned.m16n8k16.row.col.f32.f16.f16.f32 "
        "{%0,%1,%2,%3}, {%4,%5,%6,%7}, {%8,%9}, {%0,%1,%2,%3};"
        : "+f"(c[0]), "+f"(c[1]), "+f"(c[2]), "+f"(c[3])
        : "r"(a[0]), "r"(a[1]), "r"(a[2]), "r"(a[3]), "r"(b[0]), "r"(b[1]));
}

// FMA-only fast tanh (abs err ~1e-6); avoids MUFU entirely.
__device__ __forceinline__ float fast_tanh(float x) {
    float ax = fabsf(x);
    float t = fminf(ax * 2.885390082f, 30.0f);     // 2|x|*log2(e)
    float nt = -t;
    float fi = floorf(nt);
    float f = nt - fi;                              // [0,1)
    float p =              1.5253232e-5f;
    p = fmaf(p, f, 1.5403530e-4f);
    p = fmaf(p, f, 1.3333558e-3f);
    p = fmaf(p, f, 9.6181291e-3f);
    p = fmaf(p, f, 5.5504109e-2f);
    p = fmaf(p, f, 2.4022651e-1f);
    p = fmaf(p, f, 6.9314718e-1f);
    p = fmaf(p, f, 1.0f);
    int ei = (int)fi;                               // [-30, 0]
    float e = __int_as_float((ei + 127) << 23) * p; // 2^nt = e^{-2|x|}
    float d = 1.0f + e;
    float r = __int_as_float(0x7EF311C3u - __float_as_int(d));
    r = r * (2.0f - d * r);
    r = r * (2.0f - d * r);
    r = r * (2.0f - d * r);
    float y = (1.0f - e) * r;
    return copysignf(y, x);
}

// ---------------------------------------------------------------------------
// Kernel A: enc fp32 -> fp16 (hi only)
// ---------------------------------------------------------------------------
__global__ void convert_x_kernel(const float* __restrict__ X) {
    size_t i = ((size_t)blockIdx.x * 256 + threadIdx.x) * 8;
    float4 a = *(const float4*)(X + i);
    float4 b = *(const float4*)(X + i + 4);
    float v[8] = {a.x, a.y, a.z, a.w, b.x, b.y, b.z, b.w};
    __half hi[8];
    #pragma unroll
    for (int j = 0; j < 8; j++) hi[j] = __float2half_rn(v[j]);
    *(uint4*)(g_Xhi + i) = *(uint4*)hi;
}

// ---------------------------------------------------------------------------
// Kernel B: transpose + split W2 [d][u] -> [u][d] fp16 hi/lo
// ---------------------------------------------------------------------------
__global__ void convert_w_kernel(const float* __restrict__ W2) {
    __shared__ float tile[32][33];
    const int u0 = blockIdx.x * 32, d0 = blockIdx.y * 32;
    const int tx = threadIdx.x, ty = threadIdx.y;           // (32, 8)
    #pragma unroll
    for (int j = 0; j < 32; j += 8)
        tile[ty + j][tx] = W2[(size_t)(d0 + ty + j) * U_ + u0 + tx];
    __syncthreads();
    #pragma unroll
    for (int j = 0; j < 32; j += 8) {
        float v = tile[tx][ty + j];
        __half h = __float2half_rn(v);
        __half l = __float2half_rn(v - __half2float(h));
        g_Whi[(size_t)(u0 + ty + j) * D_ + d0 + tx] = h;
        g_Wlo[(size_t)(u0 + ty + j) * D_ + d0 + tx] = l;
    }
}

// ---------------------------------------------------------------------------
// Kernel C: hpb[b,u] = h@W1 + b1 + b2
// ---------------------------------------------------------------------------
__global__ void hproj_kernel(const float* __restrict__ h,
                             const float* __restrict__ W1,
                             const float* __restrict__ b1,
                             const float* __restrict__ b2) {
    __shared__ float hs[D_];
    const int b = blockIdx.y;
    const int u = blockIdx.x * 256 + threadIdx.x;
    for (int i = threadIdx.x; i < D_; i += 256) hs[i] = h[b * D_ + i];
    __syncthreads();
    float acc = 0.f;
    #pragma unroll 8
    for (int d = 0; d < D_; d++) acc = fmaf(hs[d], W1[d * U_ + u], acc);
    g_hpb[b * U_ + u] = acc + b1[u] + b2[u];
}

// ---------------------------------------------------------------------------
// Kernel D: score GEMM via mma.sync fp16, TWO products (Xhi*Whi + Xhi*Wlo),
// fused tanh/V epilogue. Grid = 2048 (row-block x u-pass), atomicAdd partial
// row sums. 3-stage cp.async pipeline, 512 threads / 16 warps, 64x32 tiles.
// ---------------------------------------------------------------------------
#define ROWB     80                       // bytes per padded smem row
#define A_SPL    (128 * ROWB)             // 10240 (single split now)
#define B_SPL    (256 * ROWB)             // 20480 per split
#define STAGE_SZ (A_SPL + 2 * B_SPL)      // 51200
#define OFF_B    A_SPL
#define NSTAGE   3
#define OFF_VH   (NSTAGE * STAGE_SZ)      // 153600
#define OFF_RED  (OFF_VH + 2048)
#define SK_SMEM  (OFF_RED + 4096)         // 159744

__global__ void __launch_bounds__(512, 1)
score_kernel(const float* __restrict__ V) {
    extern __shared__ char smem[];
    const uint32_t sb = smem_u32(smem);
    const int tid = threadIdx.x;
    const int lane = tid & 31;
    const int wid = tid >> 5;
    const int warp_m = wid >> 3;        // 0..1  (64 rows each)
    const int warp_n = wid & 7;         // 0..7  (32 cols each)
    const int row0 = (blockIdx.x >> 2) * 128;   // row block
    const int n0   = (blockIdx.x & 3) * 256;    // u-pass
    const int b = row0 >> 12;

    float* vbuf = (float*)(smem + OFF_VH);
    float* hbuf = (float*)(smem + OFF_VH + 1024);
    float* red  = (float*)(smem + OFF_RED);

    const uint32_t a_loff = (uint32_t)((lane & 15) * ROWB + (lane >> 4) * 16);
    const uint32_t b_loff = (uint32_t)(((lane & 7) + ((lane >> 4) << 3)) * ROWB
                                       + ((lane >> 3) & 1) * 16);

    if (tid < 256) {
        vbuf[tid] = V[n0 + tid];
        hbuf[tid] = g_hpb[b * U_ + n0 + tid];
    }

    float acc[4][4][4];                // 64 regs: 4 m16 x 4 n8 x 4
    #pragma unroll
    for (int mt = 0; mt < 4; mt++)
        #pragma unroll
        for (int nt = 0; nt < 4; nt++)
            #pragma unroll
            for (int c = 0; c < 4; c++) acc[mt][nt][c] = 0.f;

    // ---- stage loader (K chunk of 32 into stage s), 512 threads ----
    auto load_stage = [&](int s, int k0) {
        const uint32_t stg = sb + s * STAGE_SZ;
        {   // A: 512 tasks (128 rows x 4 16B-chunks), one per thread
            const int r = tid >> 2;
            const int c = tid & 3;
            const __half* src = g_Xhi + (size_t)(row0 + r) * D_ + k0 + c * 8;
            CP_ASYNC16(stg + r * ROWB + c * 16, src);
        }
        #pragma unroll
        for (int it = 0; it < 4; it++) {       // B: 2048 tasks
            const int task = tid + it * 512;
            const int spl = task >> 10;
            const int r   = (task >> 2) & 255;
            const int c   = task & 3;
            const __half* src = (spl ? g_Wlo : g_Whi)
                + (size_t)(n0 + r) * D_ + k0 + c * 8;
            CP_ASYNC16(stg + OFF_B + spl * B_SPL + r * ROWB + c * 16, src);
        }
    };

    load_stage(0, 0);  CP_COMMIT();
    load_stage(1, 32); CP_COMMIT();

    #pragma unroll 1
    for (int kc = 0; kc < 32; kc++) {
        CP_WAIT1();
        __syncthreads();
        if (kc + 2 < 32) load_stage((kc + 2) % NSTAGE, (kc + 2) * 32);
        CP_COMMIT();

        const uint32_t stg = sb + (kc % NSTAGE) * STAGE_SZ;
        const uint32_t aBase = stg + warp_m * 64 * ROWB + a_loff;
        const uint32_t bBase = stg + OFF_B + warp_n * 32 * ROWB + b_loff;

        #pragma unroll
        for (int k16 = 0; k16 < 2; k16++) {
            const uint32_t ko = k16 * 32;
            uint32_t af[4][4], bh[2][4], bl[2][4];
            // all 8 LDSMs up front
            #pragma unroll
            for (int i = 0; i < 2; i++) {
                ldm_x4(bh[i], bBase + i * 16 * ROWB + ko);
                ldm_x4(bl[i], bBase + B_SPL + i * 16 * ROWB + ko);
            }
            #pragma unroll
            for (int mt = 0; mt < 4; mt++)
                ldm_x4(af[mt], aBase + mt * 16 * ROWB + ko);
            // sweep 1: Xhi * Whi
            #pragma unroll
            for (int mt = 0; mt < 4; mt++)
                #pragma unroll
                for (int nt = 0; nt < 4; nt++)
                    mma_fp16(acc[mt][nt], af[mt], &bh[nt >> 1][(nt & 1) * 2]);
            // sweep 2: Xhi * Wlo
            #pragma unroll
            for (int mt = 0; mt < 4; mt++)
                #pragma unroll
                for (int nt = 0; nt < 4; nt++)
                    mma_fp16(acc[mt][nt], af[mt], &bl[nt >> 1][(nt & 1) * 2]);
        }
    }

    // ---- epilogue: fold tanh + V into per-row partials ----
    float rowsum8[8];
    #pragma unroll
    for (int j = 0; j < 8; j++) rowsum8[j] = 0.f;
    #pragma unroll
    for (int mt = 0; mt < 4; mt++)
        #pragma unroll
        for (int nt = 0; nt < 4; nt++)
            #pragma unroll
            for (int c = 0; c < 4; c++) {
                const int ul = warp_n * 32 + nt * 8 + (lane & 3) * 2 + (c & 1);
                const float s = acc[mt][nt][c] + hbuf[ul];
                rowsum8[mt * 2 + (c >> 1)] =
                    fmaf(vbuf[ul], fast_tanh(s), rowsum8[mt * 2 + (c >> 1)]);
            }

    // cross-thread reduction: quad-shfl, then 8 warp_n slices via smem
    #pragma unroll
    for (int j = 0; j < 8; j++) {
        float v = rowsum8[j];
        v += __shfl_xor_sync(0xffffffffu, v, 1);
        v += __shfl_xor_sync(0xffffffffu, v, 2);
        if ((lane & 3) == 0) {
            const int r = warp_m * 64 + (j >> 1) * 16 + (lane >> 2) + 8 * (j & 1);
            red[r * 8 + warp_n] = v;
        }
    }
    __syncthreads();
    if (tid < 128) {
        float s = 0.f;
        #pragma unroll
        for (int j = 0; j < 8; j++) s += red[tid * 8 + j];
        atomicAdd(&g_score[row0 + tid], s);   // partial over this u-pass
    }
}

// ---------------------------------------------------------------------------
// Kernel E: softmax over T per batch (bv constant -> softmax-invariant)
// ---------------------------------------------------------------------------
__global__ void softmax_kernel(float* __restrict__ wout) {
    const int b = blockIdx.x;
    const float* s = g_score + b * T_;
    float* w = wout + b * T_;
    __shared__ float red[256];
    const int tid = threadIdx.x;

    float mx = -INFINITY;
    for (int t = tid; t < T_; t += 256) mx = fmaxf(mx, s[t]);
    red[tid] = mx; __syncthreads();
    for (int o = 128; o > 0; o >>= 1) {
        if (tid < o) red[tid] = fmaxf(red[tid], red[tid + o]);
        __syncthreads();
    }
    mx = red[0]; __syncthreads();

    float sum = 0.f;
    for (int t = tid; t < T_; t += 256) {
        const float e = expf(s[t] - mx);
        w[t] = e;
        sum += e;
    }
    red[tid] = sum; __syncthreads();
    for (int o = 128; o > 0; o >>= 1) {
        if (tid < o) red[tid] += red[tid + o];
        __syncthreads();
    }
    const float inv = 1.f / red[0];
    for (int t = tid; t < T_; t += 256) w[t] *= inv;
}

// ---------------------------------------------------------------------------
// Kernel F: context[b,d] = sum_t w[b,t] * enc[b,t,d]
// ---------------------------------------------------------------------------
__global__ void context_kernel(const float* __restrict__ enc,
                               const float* __restrict__ w,
                               float* __restrict__ ctx) {
    const int b  = blockIdx.y;
    const int t0 = blockIdx.x * 128;
    const int tid = threadIdx.x;
    float c[4] = {0.f, 0.f, 0.f, 0.f};
    for (int t = t0; t < t0 + 128; t++) {
        const float wt = w[b * T_ + t];
        const float* row = enc + ((size_t)b * T_ + t) * D_;
        #pragma unroll
        for (int j = 0; j < 4; j++)
            c[j] = fmaf(wt, row[tid + j * 256], c[j]);
    }
    #pragma unroll
    for (int j = 0; j < 4; j++)
        atomicAdd(&ctx[b * D_ + tid + j * 256], c[j]);
}

// ---------------------------------------------------------------------------
extern "C" void kernel_launch(void* const* d_in, const int* in_sizes, int n_in,
                              void* d_out, int out_size) {
    const float* h   = (const float*)d_in[0];  // [B, D]
    const float* enc = (const float*)d_in[1];  // [B, T, D]
    const float* W1  = (const float*)d_in[2];  // [D, U]
    const float* b1  = (const float*)d_in[3];  // [U]
    const float* W2  = (const float*)d_in[4];  // [D, U]
    const float* b2  = (const float*)d_in[5];  // [U]
    const float* V   = (const float*)d_in[6];  // [U, 1]
    // d_in[7] = bv: softmax-invariant constant, unused.

    float* out = (float*)d_out;
    float* ctx = out;             // [B, D]
    float* wts = out + B_ * D_;   // [B, T, 1]

    cudaFuncSetAttribute(score_kernel,
                         cudaFuncAttributeMaxDynamicSharedMemorySize, SK_SMEM);

    void* scorePtr = nullptr;
    cudaGetSymbolAddress(&scorePtr, g_score);

    cudaMemsetAsync(ctx, 0, (size_t)B_ * D_ * sizeof(float));
    cudaMemsetAsync(scorePtr, 0, (size_t)M_ * sizeof(float));

    convert_x_kernel<<<(M_ * D_) / (256 * 8), 256>>>(enc);
    convert_w_kernel<<<dim3(32, 32), dim3(32, 8)>>>(W2);
    hproj_kernel<<<dim3(U_ / 256, B_), 256>>>(h, W1, b1, b2);
    score_kernel<<<4 * (M_ / 128), 512, SK_SMEM>>>(V);
    softmax_kernel<<<B_, 256>>>(wts);
    context_kernel<<<dim3(T_ / 128, B_), 256>>>(enc, wts, ctx);
}

// round 8
// speedup vs baseline: 5.5283x; 1.5803x over previous
#include <cuda_runtime.h>
#include <cuda_fp16.h>
#include <math.h>
#include <stdint.h>

// Problem constants
#define B_  16
#define T_  4096
#define D_  1024
#define U_  1024
#define M_  (B_ * T_)   // 65536 rows

// ---------------------------------------------------------------------------
// Device-global scratch (no allocations allowed)
// ---------------------------------------------------------------------------
__device__ __half g_Xhi[(size_t)M_ * D_];   // 128 MiB  (fp16 of enc)
__device__ __half g_Whi[(size_t)U_ * D_];   // W2^T [u][d] fp16
__device__ float g_hpb[B_ * U_];
__device__ float g_score[M_];

// ---------------------------------------------------------------------------
// Helpers
// ---------------------------------------------------------------------------
__device__ __forceinline__ uint32_t smem_u32(const void* p) {
    uint32_t a;
    asm("{ .reg .u64 t; cvta.to.shared.u64 t, %1; cvt.u32.u64 %0, t; }" : "=r"(a) : "l"(p));
    return a;
}
#define CP_ASYNC16(dst, src) \
    asm volatile("cp.async.cg.shared.global [%0], [%1], 16;" :: "r"(dst), "l"(src))
#define CP_COMMIT() asm volatile("cp.async.commit_group;" ::: "memory")
#define CP_WAIT1()  asm volatile("cp.async.wait_group 1;" ::: "memory")

__device__ __forceinline__ void ldm_x4(uint32_t* r, uint32_t addr) {
    asm volatile("ldmatrix.sync.aligned.m8n8.x4.shared.b16 {%0,%1,%2,%3}, [%4];"
                 : "=r"(r[0]), "=r"(r[1]), "=r"(r[2]), "=r"(r[3]) : "r"(addr));
}
__device__ __forceinline__ void mma_fp16(float* c, const uint32_t* a, const uint32_t* b) {
    asm volatile(
        "mma.sync.aligned.m16n8k16.row.col.f32.f16.f16.f32 "
        "{%0,%1,%2,%3}, {%4,%5,%6,%7}, {%8,%9}, {%0,%1,%2,%3};"
        : "+f"(c[0]), "+f"(c[1]), "+f"(c[2]), "+f"(c[3])
        : "r"(a[0]), "r"(a[1]), "r"(a[2]), "r"(a[3]), "r"(b[0]), "r"(b[1]));
}

// FMA-only fast tanh (abs err ~1e-6); avoids MUFU entirely.
__device__ __forceinline__ float fast_tanh(float x) {
    float ax = fabsf(x);
    float t = fminf(ax * 2.885390082f, 30.0f);     // 2|x|*log2(e)
    float nt = -t;
    float fi = floorf(nt);
    float f = nt - fi;                              // [0,1)
    float p =              1.5253232e-5f;
    p = fmaf(p, f, 1.5403530e-4f);
    p = fmaf(p, f, 1.3333558e-3f);
    p = fmaf(p, f, 9.6181291e-3f);
    p = fmaf(p, f, 5.5504109e-2f);
    p = fmaf(p, f, 2.4022651e-1f);
    p = fmaf(p, f, 6.9314718e-1f);
    p = fmaf(p, f, 1.0f);
    int ei = (int)fi;                               // [-30, 0]
    float e = __int_as_float((ei + 127) << 23) * p; // 2^nt = e^{-2|x|}
    float d = 1.0f + e;
    float r = __int_as_float(0x7EF311C3u - __float_as_int(d));
    r = r * (2.0f - d * r);
    r = r * (2.0f - d * r);
    r = r * (2.0f - d * r);
    float y = (1.0f - e) * r;
    return copysignf(y, x);
}

// ---------------------------------------------------------------------------
// Kernel A: enc fp32 -> fp16
// ---------------------------------------------------------------------------
__global__ void convert_x_kernel(const float* __restrict__ X) {
    size_t i = ((size_t)blockIdx.x * 256 + threadIdx.x) * 8;
    float4 a = *(const float4*)(X + i);
    float4 b = *(const float4*)(X + i + 4);
    float v[8] = {a.x, a.y, a.z, a.w, b.x, b.y, b.z, b.w};
    __half hi[8];
    #pragma unroll
    for (int j = 0; j < 8; j++) hi[j] = __float2half_rn(v[j]);
    *(uint4*)(g_Xhi + i) = *(uint4*)hi;
}

// ---------------------------------------------------------------------------
// Kernel B: transpose W2 [d][u] -> [u][d] fp16
// ---------------------------------------------------------------------------
__global__ void convert_w_kernel(const float* __restrict__ W2) {
    __shared__ float tile[32][33];
    const int u0 = blockIdx.x * 32, d0 = blockIdx.y * 32;
    const int tx = threadIdx.x, ty = threadIdx.y;           // (32, 8)
    #pragma unroll
    for (int j = 0; j < 32; j += 8)
        tile[ty + j][tx] = W2[(size_t)(d0 + ty + j) * U_ + u0 + tx];
    __syncthreads();
    #pragma unroll
    for (int j = 0; j < 32; j += 8)
        g_Whi[(size_t)(u0 + ty + j) * D_ + d0 + tx] =
            __float2half_rn(tile[tx][ty + j]);
}

// ---------------------------------------------------------------------------
// Kernel C: hpb[b,u] = h@W1 + b1 + b2
// ---------------------------------------------------------------------------
__global__ void hproj_kernel(const float* __restrict__ h,
                             const float* __restrict__ W1,
                             const float* __restrict__ b1,
                             const float* __restrict__ b2) {
    __shared__ float hs[D_];
    const int b = blockIdx.y;
    const int u = blockIdx.x * 256 + threadIdx.x;
    for (int i = threadIdx.x; i < D_; i += 256) hs[i] = h[b * D_ + i];
    __syncthreads();
    float acc = 0.f;
    #pragma unroll 8
    for (int d = 0; d < D_; d++) acc = fmaf(hs[d], W1[d * U_ + u], acc);
    g_hpb[b * U_ + u] = acc + b1[u] + b2[u];
}

// ---------------------------------------------------------------------------
// Kernel D: score GEMM via mma.sync fp16 (single product), fused tanh/V
// epilogue. Grid = 2048 (row-block x u-pass), atomicAdd partial row sums.
// K chunks of 64 (halved barrier count), 3-stage cp.async pipeline,
// 512 threads / 16 warps, 64x32 warp tiles.
// Smem rows padded to 144B (64 fp16 + 16B pad) -> conflict-free ldmatrix.
// ---------------------------------------------------------------------------
#define ROWB     144                      // 128 B data + 16 B pad
#define A_TILE   (128 * ROWB)             // 18432
#define B_TILE   (256 * ROWB)             // 36864
#define STAGE_SZ (A_TILE + B_TILE)        // 55296
#define OFF_B    A_TILE
#define NSTAGE   3
#define OFF_VH   (NSTAGE * STAGE_SZ)      // 165888
#define OFF_RED  (OFF_VH + 2048)
#define SK_SMEM  (OFF_RED + 4096)         // 172032

__global__ void __launch_bounds__(512, 1)
score_kernel(const float* __restrict__ V) {
    extern __shared__ char smem[];
    const uint32_t sb = smem_u32(smem);
    const int tid = threadIdx.x;
    const int lane = tid & 31;
    const int wid = tid >> 5;
    const int warp_m = wid >> 3;        // 0..1  (64 rows each)
    const int warp_n = wid & 7;         // 0..7  (32 cols each)
    const int row0 = (blockIdx.x >> 2) * 128;   // row block
    const int n0   = (blockIdx.x & 3) * 256;    // u-pass
    const int b = row0 >> 12;

    float* vbuf = (float*)(smem + OFF_VH);
    float* hbuf = (float*)(smem + OFF_VH + 1024);
    float* red  = (float*)(smem + OFF_RED);

    const uint32_t a_loff = (uint32_t)((lane & 15) * ROWB + (lane >> 4) * 16);
    const uint32_t b_loff = (uint32_t)(((lane & 7) + ((lane >> 4) << 3)) * ROWB
                                       + ((lane >> 3) & 1) * 16);

    if (tid < 256) {
        vbuf[tid] = V[n0 + tid];
        hbuf[tid] = g_hpb[b * U_ + n0 + tid];
    }

    float acc[4][4][4];                // 64 regs: 4 m16 x 4 n8 x 4
    #pragma unroll
    for (int mt = 0; mt < 4; mt++)
        #pragma unroll
        for (int nt = 0; nt < 4; nt++)
            #pragma unroll
            for (int c = 0; c < 4; c++) acc[mt][nt][c] = 0.f;

    // ---- stage loader (K chunk of 64 into stage s), 512 threads ----
    auto load_stage = [&](int s, int k0) {
        const uint32_t stg = sb + s * STAGE_SZ;
        #pragma unroll
        for (int it = 0; it < 2; it++) {       // A: 128 rows x 8 chunks
            const int task = tid + it * 512;
            const int r = task >> 3, c = task & 7;
            const __half* src = g_Xhi + (size_t)(row0 + r) * D_ + k0 + c * 8;
            CP_ASYNC16(stg + r * ROWB + c * 16, src);
        }
        #pragma unroll
        for (int it = 0; it < 4; it++) {       // B: 256 rows x 8 chunks
            const int task = tid + it * 512;
            const int r = task >> 3, c = task & 7;
            const __half* src = g_Whi + (size_t)(n0 + r) * D_ + k0 + c * 8;
            CP_ASYNC16(stg + OFF_B + r * ROWB + c * 16, src);
        }
    };

    load_stage(0, 0);   CP_COMMIT();
    load_stage(1, 64);  CP_COMMIT();

    #pragma unroll 1
    for (int kc = 0; kc < 16; kc++) {
        CP_WAIT1();
        __syncthreads();
        if (kc + 2 < 16) load_stage((kc + 2) % NSTAGE, (kc + 2) * 64);
        CP_COMMIT();

        const uint32_t stg = sb + (kc % NSTAGE) * STAGE_SZ;
        const uint32_t aBase = stg + warp_m * 64 * ROWB + a_loff;
        const uint32_t bBase = stg + OFF_B + warp_n * 32 * ROWB + b_loff;

        #pragma unroll
        for (int k16 = 0; k16 < 4; k16++) {
            const uint32_t ko = k16 * 32;      // 16 fp16 = 32 bytes
            uint32_t af[4][4], bf[2][4];
            #pragma unroll
            for (int i = 0; i < 2; i++)
                ldm_x4(bf[i], bBase + i * 16 * ROWB + ko);
            #pragma unroll
            for (int mt = 0; mt < 4; mt++)
                ldm_x4(af[mt], aBase + mt * 16 * ROWB + ko);
            #pragma unroll
            for (int mt = 0; mt < 4; mt++)
                #pragma unroll
                for (int nt = 0; nt < 4; nt++)
                    mma_fp16(acc[mt][nt], af[mt], &bf[nt >> 1][(nt & 1) * 2]);
        }
    }

    // ---- epilogue: fold tanh + V into per-row partials ----
    float rowsum8[8];
    #pragma unroll
    for (int j = 0; j < 8; j++) rowsum8[j] = 0.f;
    #pragma unroll
    for (int mt = 0; mt < 4; mt++)
        #pragma unroll
        for (int nt = 0; nt < 4; nt++)
            #pragma unroll
            for (int c = 0; c < 4; c++) {
                const int ul = warp_n * 32 + nt * 8 + (lane & 3) * 2 + (c & 1);
                const float s = acc[mt][nt][c] + hbuf[ul];
                rowsum8[mt * 2 + (c >> 1)] =
                    fmaf(vbuf[ul], fast_tanh(s), rowsum8[mt * 2 + (c >> 1)]);
            }

    // cross-thread reduction: quad-shfl, then 8 warp_n slices via smem
    #pragma unroll
    for (int j = 0; j < 8; j++) {
        float v = rowsum8[j];
        v += __shfl_xor_sync(0xffffffffu, v, 1);
        v += __shfl_xor_sync(0xffffffffu, v, 2);
        if ((lane & 3) == 0) {
            const int r = warp_m * 64 + (j >> 1) * 16 + (lane >> 2) + 8 * (j & 1);
            red[r * 8 + warp_n] = v;
        }
    }
    __syncthreads();
    if (tid < 128) {
        float s = 0.f;
        #pragma unroll
        for (int j = 0; j < 8; j++) s += red[tid * 8 + j];
        atomicAdd(&g_score[row0 + tid], s);   // partial over this u-pass
    }
}

// ---------------------------------------------------------------------------
// Kernel E: softmax over T per batch (bv constant -> softmax-invariant)
// ---------------------------------------------------------------------------
__global__ void softmax_kernel(float* __restrict__ wout) {
    const int b = blockIdx.x;
    const float* s = g_score + b * T_;
    float* w = wout + b * T_;
    __shared__ float red[256];
    const int tid = threadIdx.x;

    float mx = -INFINITY;
    for (int t = tid; t < T_; t += 256) mx = fmaxf(mx, s[t]);
    red[tid] = mx; __syncthreads();
    for (int o = 128; o > 0; o >>= 1) {
        if (tid < o) red[tid] = fmaxf(red[tid], red[tid + o]);
        __syncthreads();
    }
    mx = red[0]; __syncthreads();

    float sum = 0.f;
    for (int t = tid; t < T_; t += 256) {
        const float e = expf(s[t] - mx);
        w[t] = e;
        sum += e;
    }
    red[tid] = sum; __syncthreads();
    for (int o = 128; o > 0; o >>= 1) {
        if (tid < o) red[tid] += red[tid + o];
        __syncthreads();
    }
    const float inv = 1.f / red[0];
    for (int t = tid; t < T_; t += 256) w[t] *= inv;
}

// ---------------------------------------------------------------------------
// Kernel F: context[b,d] = sum_t w[b,t] * enc[b,t,d]
// ---------------------------------------------------------------------------
__global__ void context_kernel(const float* __restrict__ enc,
                               const float* __restrict__ w,
                               float* __restrict__ ctx) {
    const int b  = blockIdx.y;
    const int t0 = blockIdx.x * 128;
    const int tid = threadIdx.x;
    float c[4] = {0.f, 0.f, 0.f, 0.f};
    for (int t = t0; t < t0 + 128; t++) {
        const float wt = w[b * T_ + t];
        const float* row = enc + ((size_t)b * T_ + t) * D_;
        #pragma unroll
        for (int j = 0; j < 4; j++)
            c[j] = fmaf(wt, row[tid + j * 256], c[j]);
    }
    #pragma unroll
    for (int j = 0; j < 4; j++)
        atomicAdd(&ctx[b * D_ + tid + j * 256], c[j]);
}

// ---------------------------------------------------------------------------
extern "C" void kernel_launch(void* const* d_in, const int* in_sizes, int n_in,
                              void* d_out, int out_size) {
    const float* h   = (const float*)d_in[0];  // [B, D]
    const float* enc = (const float*)d_in[1];  // [B, T, D]
    const float* W1  = (const float*)d_in[2];  // [D, U]
    const float* b1  = (const float*)d_in[3];  // [U]
    const float* W2  = (const float*)d_in[4];  // [D, U]
    const float* b2  = (const float*)d_in[5];  // [U]
    const float* V   = (const float*)d_in[6];  // [U, 1]
    // d_in[7] = bv: softmax-invariant constant, unused.

    float* out = (float*)d_out;
    float* ctx = out;             // [B, D]
    float* wts = out + B_ * D_;   // [B, T, 1]

    cudaFuncSetAttribute(score_kernel,
                         cudaFuncAttributeMaxDynamicSharedMemorySize, SK_SMEM);

    void* scorePtr = nullptr;
    cudaGetSymbolAddress(&scorePtr, g_score);

    cudaMemsetAsync(ctx, 0, (size_t)B_ * D_ * sizeof(float));
    cudaMemsetAsync(scorePtr, 0, (size_t)M_ * sizeof(float));

    convert_x_kernel<<<(M_ * D_) / (256 * 8), 256>>>(enc);
    convert_w_kernel<<<dim3(32, 32), dim3(32, 8)>>>(W2);
    hproj_kernel<<<dim3(U_ / 256, B_), 256>>>(h, W1, b1, b2);
    score_kernel<<<4 * (M_ / 128), 512, SK_SMEM>>>(V);
    softmax_kernel<<<B_, 256>>>(wts);
    context_kernel<<<dim3(T_ / 128, B_), 256>>>(enc, wts, ctx);
}

// round 9
// speedup vs baseline: 5.6337x; 1.0191x over previous
#include <cuda_runtime.h>
#include <cuda_fp16.h>
#include <math.h>
#include <stdint.h>

// Problem constants
#define B_  16
#define T_  4096
#define D_  1024
#define U_  1024
#define M_  (B_ * T_)   // 65536 rows

// ---------------------------------------------------------------------------
// Device-global scratch (no allocations allowed)
// ---------------------------------------------------------------------------
__device__ __half g_Xhi[(size_t)M_ * D_];   // 128 MiB  (fp16 of enc)
__device__ __half g_Whi[(size_t)U_ * D_];   // W2^T [u][d] fp16
__device__ float g_hpb[B_ * U_];
__device__ float g_score[M_];

// ---------------------------------------------------------------------------
// Helpers
// ---------------------------------------------------------------------------
__device__ __forceinline__ uint32_t smem_u32(const void* p) {
    uint32_t a;
    asm("{ .reg .u64 t; cvta.to.shared.u64 t, %1; cvt.u32.u64 %0, t; }" : "=r"(a) : "l"(p));
    return a;
}
#define CP_ASYNC16(dst, src) \
    asm volatile("cp.async.cg.shared.global [%0], [%1], 16;" :: "r"(dst), "l"(src))
#define CP_COMMIT() asm volatile("cp.async.commit_group;" ::: "memory")
#define CP_WAIT1()  asm volatile("cp.async.wait_group 1;" ::: "memory")

__device__ __forceinline__ void ldm_x4(uint32_t* r, uint32_t addr) {
    asm volatile("ldmatrix.sync.aligned.m8n8.x4.shared.b16 {%0,%1,%2,%3}, [%4];"
                 : "=r"(r[0]), "=r"(r[1]), "=r"(r[2]), "=r"(r[3]) : "r"(addr));
}
__device__ __forceinline__ void mma_fp16(float* c, const uint32_t* a, const uint32_t* b) {
    asm volatile(
        "mma.sync.aligned.m16n8k16.row.col.f32.f16.f16.f32 "
        "{%0,%1,%2,%3}, {%4,%5,%6,%7}, {%8,%9}, {%0,%1,%2,%3};"
        : "+f"(c[0]), "+f"(c[1]), "+f"(c[2]), "+f"(c[3])
        : "r"(a[0]), "r"(a[1]), "r"(a[2]), "r"(a[3]), "r"(b[0]), "r"(b[1]));
}

// FMA-only fast tanh (abs err ~1e-6); avoids MUFU entirely.
__device__ __forceinline__ float fast_tanh(float x) {
    float ax = fabsf(x);
    float t = fminf(ax * 2.885390082f, 30.0f);     // 2|x|*log2(e)
    float nt = -t;
    float fi = floorf(nt);
    float f = nt - fi;                              // [0,1)
    float p =              1.5253232e-5f;
    p = fmaf(p, f, 1.5403530e-4f);
    p = fmaf(p, f, 1.3333558e-3f);
    p = fmaf(p, f, 9.6181291e-3f);
    p = fmaf(p, f, 5.5504109e-2f);
    p = fmaf(p, f, 2.4022651e-1f);
    p = fmaf(p, f, 6.9314718e-1f);
    p = fmaf(p, f, 1.0f);
    int ei = (int)fi;                               // [-30, 0]
    float e = __int_as_float((ei + 127) << 23) * p; // 2^nt = e^{-2|x|}
    float d = 1.0f + e;
    float r = __int_as_float(0x7EF311C3u - __float_as_int(d));
    r = r * (2.0f - d * r);
    r = r * (2.0f - d * r);
    r = r * (2.0f - d * r);
    float y = (1.0f - e) * r;
    return copysignf(y, x);
}

// ---------------------------------------------------------------------------
// Kernel A: enc fp32 -> fp16
// ---------------------------------------------------------------------------
__global__ void convert_x_kernel(const float* __restrict__ X) {
    size_t i = ((size_t)blockIdx.x * 256 + threadIdx.x) * 8;
    float4 a = *(const float4*)(X + i);
    float4 b = *(const float4*)(X + i + 4);
    float v[8] = {a.x, a.y, a.z, a.w, b.x, b.y, b.z, b.w};
    __half hi[8];
    #pragma unroll
    for (int j = 0; j < 8; j++) hi[j] = __float2half_rn(v[j]);
    *(uint4*)(g_Xhi + i) = *(uint4*)hi;
}

// ---------------------------------------------------------------------------
// Kernel B: transpose W2 [d][u] -> [u][d] fp16
// ---------------------------------------------------------------------------
__global__ void convert_w_kernel(const float* __restrict__ W2) {
    __shared__ float tile[32][33];
    const int u0 = blockIdx.x * 32, d0 = blockIdx.y * 32;
    const int tx = threadIdx.x, ty = threadIdx.y;           // (32, 8)
    #pragma unroll
    for (int j = 0; j < 32; j += 8)
        tile[ty + j][tx] = W2[(size_t)(d0 + ty + j) * U_ + u0 + tx];
    __syncthreads();
    #pragma unroll
    for (int j = 0; j < 32; j += 8)
        g_Whi[(size_t)(u0 + ty + j) * D_ + d0 + tx] =
            __float2half_rn(tile[tx][ty + j]);
}

// ---------------------------------------------------------------------------
// Kernel C: hpb[b,u] = h@W1 + b1 + b2
// ---------------------------------------------------------------------------
__global__ void hproj_kernel(const float* __restrict__ h,
                             const float* __restrict__ W1,
                             const float* __restrict__ b1,
                             const float* __restrict__ b2) {
    __shared__ float hs[D_];
    const int b = blockIdx.y;
    const int u = blockIdx.x * 256 + threadIdx.x;
    for (int i = threadIdx.x; i < D_; i += 256) hs[i] = h[b * D_ + i];
    __syncthreads();
    float acc = 0.f;
    #pragma unroll 8
    for (int d = 0; d < D_; d++) acc = fmaf(hs[d], W1[d * U_ + u], acc);
    g_hpb[b * U_ + u] = acc + b1[u] + b2[u];
}

// ---------------------------------------------------------------------------
// Kernel D: score GEMM via mma.sync fp16 (single product), fused tanh/V
// epilogue. Grid = 2048 (row-block x u-pass), atomicAdd partial row sums.
// K chunks of 64, 3-stage cp.async pipeline.
// 256 threads / 8 warps, 64x64 warp tiles -> LDSM/MMA ratio 0.25
// (smem crossbar drops from ~96% to ~71% of tensor time).
// Smem rows padded to 144B (64 fp16 + 16B pad) -> conflict-free ldmatrix.
// ---------------------------------------------------------------------------
#define ROWB     144                      // 128 B data + 16 B pad
#define A_TILE   (128 * ROWB)             // 18432
#define B_TILE   (256 * ROWB)             // 36864
#define STAGE_SZ (A_TILE + B_TILE)        // 55296
#define OFF_B    A_TILE
#define NSTAGE   3
#define OFF_VH   (NSTAGE * STAGE_SZ)      // 165888
#define OFF_RED  (OFF_VH + 2048)
#define SK_SMEM  (OFF_RED + 4096)         // 172032

__global__ void __launch_bounds__(256, 1)
score_kernel(const float* __restrict__ V) {
    extern __shared__ char smem[];
    const uint32_t sb = smem_u32(smem);
    const int tid = threadIdx.x;
    const int lane = tid & 31;
    const int wid = tid >> 5;
    const int warp_m = wid >> 2;        // 0..1  (64 rows each)
    const int warp_n = wid & 3;         // 0..3  (64 cols each)
    const int row0 = (blockIdx.x >> 2) * 128;   // row block
    const int n0   = (blockIdx.x & 3) * 256;    // u-pass
    const int b = row0 >> 12;

    float* vbuf = (float*)(smem + OFF_VH);
    float* hbuf = (float*)(smem + OFF_VH + 1024);
    float* red  = (float*)(smem + OFF_RED);

    const uint32_t a_loff = (uint32_t)((lane & 15) * ROWB + (lane >> 4) * 16);
    const uint32_t b_loff = (uint32_t)(((lane & 7) + ((lane >> 4) << 3)) * ROWB
                                       + ((lane >> 3) & 1) * 16);

    {   // vbuf/hbuf: 256 entries, 256 threads
        vbuf[tid] = V[n0 + tid];
        hbuf[tid] = g_hpb[b * U_ + n0 + tid];
    }

    float acc[4][8][4];                // 128 regs: 4 m16 x 8 n8 x 4
    #pragma unroll
    for (int mt = 0; mt < 4; mt++)
        #pragma unroll
        for (int nt = 0; nt < 8; nt++)
            #pragma unroll
            for (int c = 0; c < 4; c++) acc[mt][nt][c] = 0.f;

    // ---- stage loader (K chunk of 64 into stage s), 256 threads ----
    auto load_stage = [&](int s, int k0) {
        const uint32_t stg = sb + s * STAGE_SZ;
        #pragma unroll
        for (int it = 0; it < 4; it++) {       // A: 128 rows x 8 chunks
            const int task = tid + it * 256;
            const int r = task >> 3, c = task & 7;
            const __half* src = g_Xhi + (size_t)(row0 + r) * D_ + k0 + c * 8;
            CP_ASYNC16(stg + r * ROWB + c * 16, src);
        }
        #pragma unroll
        for (int it = 0; it < 8; it++) {       // B: 256 rows x 8 chunks
            const int task = tid + it * 256;
            const int r = task >> 3, c = task & 7;
            const __half* src = g_Whi + (size_t)(n0 + r) * D_ + k0 + c * 8;
            CP_ASYNC16(stg + OFF_B + r * ROWB + c * 16, src);
        }
    };

    load_stage(0, 0);   CP_COMMIT();
    load_stage(1, 64);  CP_COMMIT();

    #pragma unroll 1
    for (int kc = 0; kc < 16; kc++) {
        CP_WAIT1();
        __syncthreads();
        if (kc + 2 < 16) load_stage((kc + 2) % NSTAGE, (kc + 2) * 64);
        CP_COMMIT();

        const uint32_t stg = sb + (kc % NSTAGE) * STAGE_SZ;
        const uint32_t aBase = stg + warp_m * 64 * ROWB + a_loff;
        const uint32_t bBase = stg + OFF_B + warp_n * 64 * ROWB + b_loff;

        #pragma unroll
        for (int k16 = 0; k16 < 4; k16++) {
            const uint32_t ko = k16 * 32;      // 16 fp16 = 32 bytes
            uint32_t af[4][4], bf[4][4];
            #pragma unroll
            for (int i = 0; i < 4; i++)
                ldm_x4(bf[i], bBase + i * 16 * ROWB + ko);
            #pragma unroll
            for (int mt = 0; mt < 4; mt++)
                ldm_x4(af[mt], aBase + mt * 16 * ROWB + ko);
            #pragma unroll
            for (int mt = 0; mt < 4; mt++)
                #pragma unroll
                for (int nt = 0; nt < 8; nt++)
                    mma_fp16(acc[mt][nt], af[mt], &bf[nt >> 1][(nt & 1) * 2]);
        }
    }

    // ---- epilogue: fold tanh + V into per-row partials ----
    float rowsum8[8];
    #pragma unroll
    for (int j = 0; j < 8; j++) rowsum8[j] = 0.f;
    #pragma unroll
    for (int mt = 0; mt < 4; mt++)
        #pragma unroll
        for (int nt = 0; nt < 8; nt++)
            #pragma unroll
            for (int c = 0; c < 4; c++) {
                const int ul = warp_n * 64 + nt * 8 + (lane & 3) * 2 + (c & 1);
                const float s = acc[mt][nt][c] + hbuf[ul];
                rowsum8[mt * 2 + (c >> 1)] =
                    fmaf(vbuf[ul], fast_tanh(s), rowsum8[mt * 2 + (c >> 1)]);
            }

    // cross-thread reduction: quad-shfl, then 4 warp_n slices via smem
    #pragma unroll
    for (int j = 0; j < 8; j++) {
        float v = rowsum8[j];
        v += __shfl_xor_sync(0xffffffffu, v, 1);
        v += __shfl_xor_sync(0xffffffffu, v, 2);
        if ((lane & 3) == 0) {
            const int r = warp_m * 64 + (j >> 1) * 16 + (lane >> 2) + 8 * (j & 1);
            red[r * 4 + warp_n] = v;
        }
    }
    __syncthreads();
    if (tid < 128)
        atomicAdd(&g_score[row0 + tid],
                  red[tid * 4 + 0] + red[tid * 4 + 1]
                + red[tid * 4 + 2] + red[tid * 4 + 3]);
}

// ---------------------------------------------------------------------------
// Kernel E: softmax over T per batch (bv constant -> softmax-invariant)
// ---------------------------------------------------------------------------
__global__ void softmax_kernel(float* __restrict__ wout) {
    const int b = blockIdx.x;
    const float* s = g_score + b * T_;
    float* w = wout + b * T_;
    __shared__ float red[256];
    const int tid = threadIdx.x;

    float mx = -INFINITY;
    for (int t = tid; t < T_; t += 256) mx = fmaxf(mx, s[t]);
    red[tid] = mx; __syncthreads();
    for (int o = 128; o > 0; o >>= 1) {
        if (tid < o) red[tid] = fmaxf(red[tid], red[tid + o]);
        __syncthreads();
    }
    mx = red[0]; __syncthreads();

    float sum = 0.f;
    for (int t = tid; t < T_; t += 256) {
        const float e = expf(s[t] - mx);
        w[t] = e;
        sum += e;
    }
    red[tid] = sum; __syncthreads();
    for (int o = 128; o > 0; o >>= 1) {
        if (tid < o) red[tid] += red[tid + o];
        __syncthreads();
    }
    const float inv = 1.f / red[0];
    for (int t = tid; t < T_; t += 256) w[t] *= inv;
}

// ---------------------------------------------------------------------------
// Kernel F: context[b,d] = sum_t w[b,t] * enc_fp16[b,t,d]  (halved traffic)
// ---------------------------------------------------------------------------
__global__ void context_kernel(const float* __restrict__ w,
                               float* __restrict__ ctx) {
    const int b  = blockIdx.y;
    const int t0 = blockIdx.x * 128;
    const int tid = threadIdx.x;
    float c[4] = {0.f, 0.f, 0.f, 0.f};
    for (int t = t0; t < t0 + 128; t++) {
        const float wt = w[b * T_ + t];
        const __half* row = g_Xhi + ((size_t)b * T_ + t) * D_;
        #pragma unroll
        for (int j = 0; j < 4; j++)
            c[j] = fmaf(wt, __half2float(row[tid + j * 256]), c[j]);
    }
    #pragma unroll
    for (int j = 0; j < 4; j++)
        atomicAdd(&ctx[b * D_ + tid + j * 256], c[j]);
}

// ---------------------------------------------------------------------------
extern "C" void kernel_launch(void* const* d_in, const int* in_sizes, int n_in,
                              void* d_out, int out_size) {
    const float* h   = (const float*)d_in[0];  // [B, D]
    const float* enc = (const float*)d_in[1];  // [B, T, D]
    const float* W1  = (const float*)d_in[2];  // [D, U]
    const float* b1  = (const float*)d_in[3];  // [U]
    const float* W2  = (const float*)d_in[4];  // [D, U]
    const float* b2  = (const float*)d_in[5];  // [U]
    const float* V   = (const float*)d_in[6];  // [U, 1]
    // d_in[7] = bv: softmax-invariant constant, unused.

    float* out = (float*)d_out;
    float* ctx = out;             // [B, D]
    float* wts = out + B_ * D_;   // [B, T, 1]

    cudaFuncSetAttribute(score_kernel,
                         cudaFuncAttributeMaxDynamicSharedMemorySize, SK_SMEM);

    void* scorePtr = nullptr;
    cudaGetSymbolAddress(&scorePtr, g_score);

    cudaMemsetAsync(ctx, 0, (size_t)B_ * D_ * sizeof(float));
    cudaMemsetAsync(scorePtr, 0, (size_t)M_ * sizeof(float));

    convert_x_kernel<<<(M_ * D_) / (256 * 8), 256>>>(enc);
    convert_w_kernel<<<dim3(32, 32), dim3(32, 8)>>>(W2);
    hproj_kernel<<<dim3(U_ / 256, B_), 256>>>(h, W1, b1, b2);
    score_kernel<<<4 * (M_ / 128), 256, SK_SMEM>>>(V);
    softmax_kernel<<<B_, 256>>>(wts);
    context_kernel<<<dim3(T_ / 128, B_), 256>>>(wts, ctx);
}